// round 5
// baseline (speedup 1.0000x reference)
#include <cuda_runtime.h>
#include <cstdint>

#define N_TOK 4096
#define DIM   1024
#define HID   1024
#define NE    8
#define NSEG  9

// ---------------- scratch ---------------------------------------------------
__device__ int    g_cnt[NSEG];
__device__ int    g_assign_token[NE * N_TOK];
__device__ int    g_assign_slot [NE * N_TOK];
__device__ int    g_top_e[N_TOK * 2];
__device__ float  g_top_w[N_TOK * 2];
__device__ int8_t g_Xq1[(size_t)N_TOK * DIM];
__device__ int8_t g_Xq2[(size_t)N_TOK * DIM];
__device__ float  g_sX[N_TOK];
// 27 matrices [n][k] (transposed): Wg[0..7], Wu[8..15], Wd[16..23], sg=24, su=25, sd=26
__device__ int8_t g_Wq1[(size_t)27 * DIM * HID];
__device__ int8_t g_Wq2[(size_t)27 * DIM * HID];
__device__ float  g_sW[27 * 1024];
__device__ float  g_hbuf[(size_t)NSEG * N_TOK * HID];
__device__ int8_t g_Hq1[(size_t)NSEG * N_TOK * HID];
__device__ int8_t g_Hq2[(size_t)NSEG * N_TOK * HID];
__device__ float  g_sH[NSEG * N_TOK];
__device__ float  g_rbuf[(size_t)3 * N_TOK * DIM];

// ---------------- helpers ---------------------------------------------------
__device__ __forceinline__ uint32_t smem_u32(const void* p) {
    uint32_t a;
    asm("{ .reg .u64 t; cvta.to.shared.u64 t, %1; cvt.u32.u64 %0, t; }"
        : "=r"(a) : "l"(p));
    return a;
}
#define CP_ASYNC16(dst, src) \
    asm volatile("cp.async.cg.shared.global [%0], [%1], 16;" :: "r"(dst), "l"(src))
#define CP_COMMIT() asm volatile("cp.async.commit_group;" ::: "memory")
#define CP_WAIT(n)  asm volatile("cp.async.wait_group %0;" :: "n"(n) : "memory")

__device__ __forceinline__ void ldsm_x4(uint32_t* r, uint32_t addr) {
    asm volatile("ldmatrix.sync.aligned.m8n8.x4.shared.b16 {%0,%1,%2,%3}, [%4];"
        : "=r"(r[0]), "=r"(r[1]), "=r"(r[2]), "=r"(r[3]) : "r"(addr));
}
__device__ __forceinline__ void ldsm_x2(uint32_t* r, uint32_t addr) {
    asm volatile("ldmatrix.sync.aligned.m8n8.x2.shared.b16 {%0,%1}, [%2];"
        : "=r"(r[0]), "=r"(r[1]) : "r"(addr));
}
__device__ __forceinline__ void mma_s8(int* d, const uint32_t* a, const uint32_t* b) {
    asm volatile(
        "mma.sync.aligned.m16n8k32.row.col.s32.s8.s8.s32 "
        "{%0,%1,%2,%3}, {%4,%5,%6,%7}, {%8,%9}, {%0,%1,%2,%3};"
        : "+r"(d[0]), "+r"(d[1]), "+r"(d[2]), "+r"(d[3])
        : "r"(a[0]), "r"(a[1]), "r"(a[2]), "r"(a[3]), "r"(b[0]), "r"(b[1]));
}
__device__ __forceinline__ float silu(float g) { return g / (1.f + __expf(-g)); }

__device__ __forceinline__ void q1(float v, float inv, int& a1, int& a2) {
    float q = v * inv;
    a1 = __float2int_rn(q);
    float r = q - (float)a1;
    a2 = __float2int_rn(r * 256.f);
    a2 = max(-127, min(127, a2));
}
__device__ __forceinline__ void q4pack(float4 v, float inv, uint32_t& o1, uint32_t& o2) {
    int a1x, a2x, a1y, a2y, a1z, a2z, a1w, a2w;
    q1(v.x, inv, a1x, a2x); q1(v.y, inv, a1y, a2y);
    q1(v.z, inv, a1z, a2z); q1(v.w, inv, a1w, a2w);
    o1 = (a1x & 255) | ((a1y & 255) << 8) | ((a1z & 255) << 16) | ((a1w & 255) << 24);
    o2 = (a2x & 255) | ((a2y & 255) << 8) | ((a2z & 255) << 16) | ((a2w & 255) << 24);
}

__device__ __forceinline__ const float* pick_src(
    int m, const float* Wg, const float* Wu, const float* Wd,
    const float* sg, const float* su, const float* sd)
{
    if (m < 8)  return Wg + (size_t)m * DIM * HID;
    if (m < 16) return Wu + (size_t)(m - 8) * DIM * HID;
    if (m < 24) return Wd + (size_t)(m - 16) * DIM * HID;
    if (m == 24) return sg;
    if (m == 25) return su;
    return sd;
}

// ---------------- small kernels ---------------------------------------------
__global__ void zero_kernel() {
    int t = threadIdx.x;
    if (t < NE) g_cnt[t] = 0;
    if (t == NE) g_cnt[NE] = N_TOK;
}

// quantize X: warp per token, 2-slice s8 + per-row scale
__global__ __launch_bounds__(256) void quant_x_kernel(const float* __restrict__ X) {
    const int warp = threadIdx.x >> 5, lane = threadIdx.x & 31;
    const int t = blockIdx.x * 8 + warp;
    const float4* xr = (const float4*)(X + (size_t)t * DIM);
    float4 xv[8];
    float mx = 0.f;
    #pragma unroll
    for (int i = 0; i < 8; i++) {
        xv[i] = xr[lane + 32 * i];
        mx = fmaxf(mx, fmaxf(fmaxf(fabsf(xv[i].x), fabsf(xv[i].y)),
                             fmaxf(fabsf(xv[i].z), fabsf(xv[i].w))));
    }
    #pragma unroll
    for (int o = 16; o; o >>= 1) mx = fmaxf(mx, __shfl_xor_sync(~0u, mx, o));
    mx = fmaxf(mx, 1e-30f);
    const float s = mx / 127.f, inv = 127.f / mx;
    uint32_t* r1 = (uint32_t*)(g_Xq1 + (size_t)t * DIM);
    uint32_t* r2 = (uint32_t*)(g_Xq2 + (size_t)t * DIM);
    #pragma unroll
    for (int i = 0; i < 8; i++) {
        uint32_t o1, o2;
        q4pack(xv[i], inv, o1, o2);
        r1[lane + 32 * i] = o1;
        r2[lane + 32 * i] = o2;
    }
    if (lane == 0) g_sX[t] = s;
}

// per-output-column max of each weight matrix -> scale
__global__ void colmax_kernel(
    const float* __restrict__ Wg, const float* __restrict__ Wu,
    const float* __restrict__ Wd, const float* __restrict__ sg,
    const float* __restrict__ su, const float* __restrict__ sd)
{
    const int m = blockIdx.y;
    const float* src = pick_src(m, Wg, Wu, Wd, sg, su, sd);
    const int n = blockIdx.x * 256 + threadIdx.x;
    float mx = 0.f;
    #pragma unroll 8
    for (int k = 0; k < 1024; k++)
        mx = fmaxf(mx, fabsf(src[(size_t)k * 1024 + n]));
    g_sW[m * 1024 + n] = fmaxf(mx, 1e-30f) / 127.f;
}

// transpose [k][n] -> [n][k] and quantize to 2-slice s8
__global__ void quant_w_kernel(
    const float* __restrict__ Wg, const float* __restrict__ Wu,
    const float* __restrict__ Wd, const float* __restrict__ sg,
    const float* __restrict__ su, const float* __restrict__ sd)
{
    __shared__ float tbuf[32][33];
    const int m = blockIdx.z;
    const float* src = pick_src(m, Wg, Wu, Wd, sg, su, sd);
    const int kt = blockIdx.y * 32, nt = blockIdx.x * 32;
    const int tx = threadIdx.x, ty = threadIdx.y;
    tbuf[ty][tx] = src[(size_t)(kt + ty) * 1024 + nt + tx];
    __syncthreads();
    float v = tbuf[tx][ty];                 // = src[kt+tx][nt+ty]
    const int n = nt + ty, k = kt + tx;
    const float inv = 1.f / g_sW[m * 1024 + n];
    int a1, a2;
    q1(v, inv, a1, a2);
    size_t o = (size_t)m * (DIM * HID) + (size_t)n * 1024 + k;
    g_Wq1[o] = (int8_t)a1;
    g_Wq2[o] = (int8_t)a2;
}

// router
__global__ __launch_bounds__(256) void router_kernel(
    const float* __restrict__ X, const float* __restrict__ Wr,
    const float* __restrict__ loop_table, const int* __restrict__ loop_idx)
{
    __shared__ float4 sW[NE][256];
    __shared__ float s_bias[NE];
    const int tid = threadIdx.x, warp = tid >> 5, lane = tid & 31;

    for (int i = tid; i < NE * 256; i += 256) {
        int e = i >> 8, k4 = i & 255;
        sW[e][k4] = make_float4(Wr[(size_t)(k4 * 4 + 0) * NE + e],
                                Wr[(size_t)(k4 * 4 + 1) * NE + e],
                                Wr[(size_t)(k4 * 4 + 2) * NE + e],
                                Wr[(size_t)(k4 * 4 + 3) * NE + e]);
    }
    const float* le = loop_table + (size_t)loop_idx[0] * DIM;
    float b = 0.f;
    for (int d = lane; d < DIM; d += 32)
        b += le[d] * Wr[(size_t)(DIM + d) * NE + warp];
    #pragma unroll
    for (int o = 16; o; o >>= 1) b += __shfl_xor_sync(~0u, b, o);
    if (lane == 0) s_bias[warp] = b;
    __syncthreads();

    #pragma unroll 1
    for (int rep = 0; rep < 4; rep++) {
        const int t = blockIdx.x * 32 + warp * 4 + rep;
        const float4* xr = (const float4*)(X + (size_t)t * DIM);
        float4 xv[8];
        #pragma unroll
        for (int i = 0; i < 8; i++) xv[i] = xr[lane + 32 * i];
        float acc[NE];
        #pragma unroll
        for (int e = 0; e < NE; e++) {
            float a = 0.f;
            #pragma unroll
            for (int i = 0; i < 8; i++) {
                float4 w = sW[e][lane + 32 * i];
                a += xv[i].x * w.x + xv[i].y * w.y + xv[i].z * w.z + xv[i].w * w.w;
            }
            acc[e] = a;
        }
        #pragma unroll
        for (int e = 0; e < NE; e++)
            #pragma unroll
            for (int o = 16; o; o >>= 1) acc[e] += __shfl_xor_sync(~0u, acc[e], o);

        if (lane == 0) {
            float p[NE];
            #pragma unroll
            for (int e = 0; e < NE; e++)
                p[e] = 1.f / (1.f + expf(-(acc[e] + s_bias[e])));
            int i0 = 0; float v0 = p[0];
            #pragma unroll
            for (int e = 1; e < NE; e++) if (p[e] > v0) { v0 = p[e]; i0 = e; }
            int i1 = -1; float v1 = -1e30f;
            #pragma unroll
            for (int e = 0; e < NE; e++) {
                if (e == i0) continue;
                if (p[e] > v1) { v1 = p[e]; i1 = e; }
            }
            g_top_e[t * 2 + 0] = i0;  g_top_e[t * 2 + 1] = i1;
            g_top_w[t * 2 + 0] = v0;  g_top_w[t * 2 + 1] = v1;
        }
    }
}

__global__ void dispatch_kernel() {
    int t = blockIdx.x * blockDim.x + threadIdx.x;
    if (t >= N_TOK) return;
    #pragma unroll
    for (int k = 0; k < 2; k++) {
        int e = g_top_e[t * 2 + k];
        int pos = atomicAdd(&g_cnt[e], 1);
        g_assign_token[e * N_TOK + pos] = t;
        g_assign_slot [e * N_TOK + pos] = k;
    }
}

// ---------------- GEMM1: Xq @ {Wg,Wu}[e] (s8 2-slice), SiLU -> fp32 h -------
// Block 128m x (64 gate + 64 up), K chunks of 32, 3-stage cp.async.
// smem pitch 48B per 32B row; warps 4m x 2n (warp = 32m x 32n per matrix).
#define Q1_A1  0u
#define Q1_A2  6144u
#define Q1_BG1 12288u
#define Q1_BG2 15360u
#define Q1_BU1 18432u
#define Q1_BU2 21504u
#define Q1_STG 24576u

__global__ __launch_bounds__(256) void gemm1_kernel() {
    extern __shared__ char sm[];
    __shared__ int   s_token[128];
    __shared__ float s_sx[128], s_sg[64], s_su[64];

    const int e   = blockIdx.z;
    const int cnt = g_cnt[e];
    const int m0  = blockIdx.y * 128;
    if (m0 >= cnt) return;
    const int n0  = blockIdx.x * 64;
    const int tid = threadIdx.x, wid = tid >> 5, lane = tid & 31;

    const int ig = (e < NE) ? e : 24;
    const int iu = (e < NE) ? 8 + e : 25;

    if (tid < 128) {
        int r = m0 + tid;
        int tok = (e < NE) ? ((r < cnt) ? g_assign_token[e * N_TOK + r] : 0) : r;
        s_token[tid] = tok;
        s_sx[tid] = g_sX[tok];
    } else if (tid < 192) {
        s_sg[tid - 128] = g_sW[ig * 1024 + n0 + tid - 128];
    } else {
        s_su[tid - 192] = g_sW[iu * 1024 + n0 + tid - 192];
    }
    __syncthreads();
    const uint32_t sb = smem_u32(sm);

    // loader roles: 4 cp.async / thread / stage
    const int arow = tid >> 1, ahalf = tid & 1;
    const char* aSrc1 = (const char*)(g_Xq1 + (size_t)s_token[arow] * DIM) + ahalf * 16;
    const char* aSrc2 = (const char*)(g_Xq2 + (size_t)s_token[arow] * DIM) + ahalf * 16;
    const uint32_t aDst1 = sb + Q1_A1 + arow * 48 + ahalf * 16;
    const uint32_t aDst2 = sb + Q1_A2 + arow * 48 + ahalf * 16;
    const int brow = (tid >> 1) & 63, bhalf = tid & 1;
    const bool sl1 = tid < 128;
    const char* gSrc = (const char*)((sl1 ? g_Wq1 : g_Wq2) + (size_t)ig * DIM * HID
                                     + (size_t)(n0 + brow) * 1024) + bhalf * 16;
    const char* uSrc = (const char*)((sl1 ? g_Wq1 : g_Wq2) + (size_t)iu * DIM * HID
                                     + (size_t)(n0 + brow) * 1024) + bhalf * 16;
    const uint32_t gDst = sb + (sl1 ? Q1_BG1 : Q1_BG2) + brow * 48 + bhalf * 16;
    const uint32_t uDst = sb + (sl1 ? Q1_BU1 : Q1_BU2) + brow * 48 + bhalf * 16;

#define Q1_LOAD(k0, buf) do { \
        uint32_t _o = (uint32_t)(buf) * Q1_STG; \
        CP_ASYNC16(aDst1 + _o, aSrc1 + (k0)); \
        CP_ASYNC16(aDst2 + _o, aSrc2 + (k0)); \
        CP_ASYNC16(gDst + _o, gSrc + (k0)); \
        CP_ASYNC16(uDst + _o, uSrc + (k0)); \
        CP_COMMIT(); } while (0)

    const int wm = (wid & 3) * 32, wn = (wid >> 2) * 32;
    const uint32_t aB1 = sb + Q1_A1 + (wm + (lane & 15)) * 48 + (lane >> 4) * 16;
    const uint32_t aB2 = sb + Q1_A2 + (wm + (lane & 15)) * 48 + (lane >> 4) * 16;
    const uint32_t bOff = (wn + (lane & 7)) * 48 + ((lane >> 3) & 1) * 16;
    const uint32_t bG1 = sb + Q1_BG1 + bOff;
    const uint32_t bG2 = sb + Q1_BG2 + bOff;
    const uint32_t bU1 = sb + Q1_BU1 + bOff;
    const uint32_t bU2 = sb + Q1_BU2 + bOff;

    int accG1[2][4][4], accG2[2][4][4], accU1[2][4][4], accU2[2][4][4];
    #pragma unroll
    for (int i = 0; i < 2; i++)
        #pragma unroll
        for (int j = 0; j < 4; j++)
            #pragma unroll
            for (int q = 0; q < 4; q++) {
                accG1[i][j][q] = 0; accG2[i][j][q] = 0;
                accU1[i][j][q] = 0; accU2[i][j][q] = 0;
            }

    Q1_LOAD(0, 0);
    Q1_LOAD(32, 1);
    CP_WAIT(1); __syncthreads();

    int cur = 0;
    for (int s = 0; s < 32; s++) {
        int ldb = cur + 2; if (ldb >= 3) ldb -= 3;
        if (s + 2 < 32) Q1_LOAD((s + 2) * 32, ldb);

        const uint32_t off = (uint32_t)cur * Q1_STG;
        uint32_t a1[2][4], a2[2][4], bg1[4][2], bg2[4][2], bu1[4][2], bu2[4][2];
        #pragma unroll
        for (int i = 0; i < 2; i++) {
            ldsm_x4(a1[i], aB1 + off + i * 768);
            ldsm_x4(a2[i], aB2 + off + i * 768);
        }
        #pragma unroll
        for (int j = 0; j < 4; j++) {
            ldsm_x2(bg1[j], bG1 + off + j * 384);
            ldsm_x2(bg2[j], bG2 + off + j * 384);
            ldsm_x2(bu1[j], bU1 + off + j * 384);
            ldsm_x2(bu2[j], bU2 + off + j * 384);
        }
        #pragma unroll
        for (int i = 0; i < 2; i++)
            #pragma unroll
            for (int j = 0; j < 4; j++) {
                mma_s8(accG1[i][j], a1[i], bg1[j]);
                mma_s8(accG2[i][j], a1[i], bg2[j]);
                mma_s8(accG2[i][j], a2[i], bg1[j]);
                mma_s8(accU1[i][j], a1[i], bu1[j]);
                mma_s8(accU2[i][j], a1[i], bu2[j]);
                mma_s8(accU2[i][j], a2[i], bu1[j]);
            }
        if (s + 2 < 32) CP_WAIT(1); else CP_WAIT(0);
        __syncthreads();
        cur++; if (cur == 3) cur = 0;
    }

    const float inv256 = 1.f / 256.f;
    const int qr = lane >> 2, r4 = lane & 3;
    #pragma unroll
    for (int i = 0; i < 2; i++) {
        const int lr0 = wm + i * 16 + qr, lr1 = lr0 + 8;
        const bool ok0 = (m0 + lr0) < cnt, ok1 = (m0 + lr1) < cnt;
        const float sx0 = s_sx[lr0], sx1 = s_sx[lr1];
        float* h0 = g_hbuf + ((size_t)e * N_TOK + m0 + lr0) * HID + n0;
        float* h1 = g_hbuf + ((size_t)e * N_TOK + m0 + lr1) * HID + n0;
        #pragma unroll
        for (int j = 0; j < 4; j++) {
            const int col = wn + j * 8 + r4 * 2;
            const float sg0 = s_sg[col], sg1 = s_sg[col + 1];
            const float su0 = s_su[col], su1 = s_su[col + 1];
            float g00 = sx0 * sg0 * ((float)accG1[i][j][0] + (float)accG2[i][j][0] * inv256);
            float g01 = sx0 * sg1 * ((float)accG1[i][j][1] + (float)accG2[i][j][1] * inv256);
            float g10 = sx1 * sg0 * ((float)accG1[i][j][2] + (float)accG2[i][j][2] * inv256);
            float g11 = sx1 * sg1 * ((float)accG1[i][j][3] + (float)accG2[i][j][3] * inv256);
            float u00 = sx0 * su0 * ((float)accU1[i][j][0] + (float)accU2[i][j][0] * inv256);
            float u01 = sx0 * su1 * ((float)accU1[i][j][1] + (float)accU2[i][j][1] * inv256);
            float u10 = sx1 * su0 * ((float)accU1[i][j][2] + (float)accU2[i][j][2] * inv256);
            float u11 = sx1 * su1 * ((float)accU1[i][j][3] + (float)accU2[i][j][3] * inv256);
            if (ok0) *(float2*)(h0 + col) = make_float2(silu(g00) * u00, silu(g01) * u01);
            if (ok1) *(float2*)(h1 + col) = make_float2(silu(g10) * u10, silu(g11) * u11);
        }
    }
#undef Q1_LOAD
}

// quantize h rows (only valid rows per segment)
__global__ __launch_bounds__(256) void quant_h_kernel() {
    const int warp = threadIdx.x >> 5, lane = threadIdx.x & 31;
    const int row = blockIdx.x * 8 + warp;
    const int e = row >> 12, r = row & (N_TOK - 1);
    if (r >= g_cnt[e]) return;
    const float4* xr = (const float4*)(g_hbuf + (size_t)row * HID);
    float4 xv[8];
    float mx = 0.f;
    #pragma unroll
    for (int i = 0; i < 8; i++) {
        xv[i] = xr[lane + 32 * i];
        mx = fmaxf(mx, fmaxf(fmaxf(fabsf(xv[i].x), fabsf(xv[i].y)),
                             fmaxf(fabsf(xv[i].z), fabsf(xv[i].w))));
    }
    #pragma unroll
    for (int o = 16; o; o >>= 1) mx = fmaxf(mx, __shfl_xor_sync(~0u, mx, o));
    mx = fmaxf(mx, 1e-30f);
    const float s = mx / 127.f, inv = 127.f / mx;
    uint32_t* r1 = (uint32_t*)(g_Hq1 + (size_t)row * HID);
    uint32_t* r2 = (uint32_t*)(g_Hq2 + (size_t)row * HID);
    #pragma unroll
    for (int i = 0; i < 8; i++) {
        uint32_t o1, o2;
        q4pack(xv[i], inv, o1, o2);
        r1[lane + 32 * i] = o1;
        r2[lane + 32 * i] = o2;
    }
    if (lane == 0) g_sH[row] = s;
}

// ---------------- GEMM2: Hq @ Wd[e] -> scattered fp32 rbuf ------------------
// Block 128m x 128n, warps 4m x 2n (warp = 32m x 64n).
#define Q2_A1 0u
#define Q2_A2 6144u
#define Q2_B1 12288u
#define Q2_B2 18432u
#define Q2_STG 24576u

__global__ __launch_bounds__(256) void gemm2_kernel() {
    extern __shared__ char sm[];
    __shared__ int   s_dst[128];
    __shared__ float s_sh[128], s_sd[128];

    const int e   = blockIdx.z;
    const int cnt = g_cnt[e];
    const int m0  = blockIdx.y * 128;
    if (m0 >= cnt) return;
    const int n0  = blockIdx.x * 128;
    const int tid = threadIdx.x, wid = tid >> 5, lane = tid & 31;

    const int id = (e < NE) ? 16 + e : 26;

    if (tid < 128) {
        int r = m0 + tid, dst = 0;
        if (r < cnt) {
            if (e < NE)
                dst = g_assign_slot[e * N_TOK + r] * N_TOK + g_assign_token[e * N_TOK + r];
            else
                dst = 2 * N_TOK + r;
        }
        s_dst[tid] = dst;
        s_sh[tid] = g_sH[e * N_TOK + m0 + tid];
    } else {
        s_sd[tid - 128] = g_sW[id * 1024 + n0 + tid - 128];
    }
    __syncthreads();
    const uint32_t sb = smem_u32(sm);

    const int arow = tid >> 1, ahalf = tid & 1;
    const char* aSrc1 = (const char*)(g_Hq1 + ((size_t)e * N_TOK + m0 + arow) * HID) + ahalf * 16;
    const char* aSrc2 = (const char*)(g_Hq2 + ((size_t)e * N_TOK + m0 + arow) * HID) + ahalf * 16;
    const uint32_t aDst1 = sb + Q2_A1 + arow * 48 + ahalf * 16;
    const uint32_t aDst2 = sb + Q2_A2 + arow * 48 + ahalf * 16;
    const char* bSrc1 = (const char*)(g_Wq1 + (size_t)id * DIM * HID
                                      + (size_t)(n0 + arow) * 1024) + ahalf * 16;
    const char* bSrc2 = (const char*)(g_Wq2 + (size_t)id * DIM * HID
                                      + (size_t)(n0 + arow) * 1024) + ahalf * 16;
    const uint32_t bDst1 = sb + Q2_B1 + arow * 48 + ahalf * 16;
    const uint32_t bDst2 = sb + Q2_B2 + arow * 48 + ahalf * 16;

#define Q2_LOAD(k0, buf) do { \
        uint32_t _o = (uint32_t)(buf) * Q2_STG; \
        CP_ASYNC16(aDst1 + _o, aSrc1 + (k0)); \
        CP_ASYNC16(aDst2 + _o, aSrc2 + (k0)); \
        CP_ASYNC16(bDst1 + _o, bSrc1 + (k0)); \
        CP_ASYNC16(bDst2 + _o, bSrc2 + (k0)); \
        CP_COMMIT(); } while (0)

    const int wm = (wid & 3) * 32, wn = (wid >> 2) * 64;
    const uint32_t aB1 = sb + Q2_A1 + (wm + (lane & 15)) * 48 + (lane >> 4) * 16;
    const uint32_t aB2 = sb + Q2_A2 + (wm + (lane & 15)) * 48 + (lane >> 4) * 16;
    const uint32_t bOff = (wn + (lane & 7)) * 48 + ((lane >> 3) & 1) * 16;
    const uint32_t bB1 = sb + Q2_B1 + bOff;
    const uint32_t bB2 = sb + Q2_B2 + bOff;

    int acc1[2][8][4], acc2[2][8][4];
    #pragma unroll
    for (int i = 0; i < 2; i++)
        #pragma unroll
        for (int j = 0; j < 8; j++)
            #pragma unroll
            for (int q = 0; q < 4; q++) { acc1[i][j][q] = 0; acc2[i][j][q] = 0; }

    Q2_LOAD(0, 0);
    Q2_LOAD(32, 1);
    CP_WAIT(1); __syncthreads();

    int cur = 0;
    for (int s = 0; s < 32; s++) {
        int ldb = cur + 2; if (ldb >= 3) ldb -= 3;
        if (s + 2 < 32) Q2_LOAD((s + 2) * 32, ldb);

        const uint32_t off = (uint32_t)cur * Q2_STG;
        uint32_t a1[2][4], a2[2][4], b1[8][2], b2[8][2];
        #pragma unroll
        for (int i = 0; i < 2; i++) {
            ldsm_x4(a1[i], aB1 + off + i * 768);
            ldsm_x4(a2[i], aB2 + off + i * 768);
        }
        #pragma unroll
        for (int j = 0; j < 8; j++) {
            ldsm_x2(b1[j], bB1 + off + j * 384);
            ldsm_x2(b2[j], bB2 + off + j * 384);
        }
        #pragma unroll
        for (int i = 0; i < 2; i++)
            #pragma unroll
            for (int j = 0; j < 8; j++) {
                mma_s8(acc1[i][j], a1[i], b1[j]);
                mma_s8(acc2[i][j], a1[i], b2[j]);
                mma_s8(acc2[i][j], a2[i], b1[j]);
            }
        if (s + 2 < 32) CP_WAIT(1); else CP_WAIT(0);
        __syncthreads();
        cur++; if (cur == 3) cur = 0;
    }

    const float inv256 = 1.f / 256.f;
    const int qr = lane >> 2, r4 = lane & 3;
    #pragma unroll
    for (int i = 0; i < 2; i++) {
        const int lr0 = wm + i * 16 + qr, lr1 = lr0 + 8;
        const bool ok0 = (m0 + lr0) < cnt, ok1 = (m0 + lr1) < cnt;
        const float sh0 = s_sh[lr0], sh1 = s_sh[lr1];
        float* d0 = g_rbuf + (size_t)s_dst[lr0] * DIM + n0;
        float* d1 = g_rbuf + (size_t)s_dst[lr1] * DIM + n0;
        #pragma unroll
        for (int j = 0; j < 8; j++) {
            const int col = wn + j * 8 + r4 * 2;
            const float sd0 = s_sd[col], sd1 = s_sd[col + 1];
            float c00 = sh0 * sd0 * ((float)acc1[i][j][0] + (float)acc2[i][j][0] * inv256);
            float c01 = sh0 * sd1 * ((float)acc1[i][j][1] + (float)acc2[i][j][1] * inv256);
            float c10 = sh1 * sd0 * ((float)acc1[i][j][2] + (float)acc2[i][j][2] * inv256);
            float c11 = sh1 * sd1 * ((float)acc1[i][j][3] + (float)acc2[i][j][3] * inv256);
            if (ok0) *(float2*)(d0 + col) = make_float2(c00, c01);
            if (ok1) *(float2*)(d1 + col) = make_float2(c10, c11);
        }
    }
#undef Q2_LOAD
}

// ---------------- combine ---------------------------------------------------
__global__ void combine_kernel(float* __restrict__ out) {
    int i4 = blockIdx.x * 256 + threadIdx.x;
    int t  = i4 >> 8;
    float w0 = g_top_w[2 * t], w1 = g_top_w[2 * t + 1];
    float4 a = ((const float4*)g_rbuf)[i4];
    float4 b = ((const float4*)g_rbuf)[(size_t)(N_TOK * DIM / 4) + i4];
    float4 c = ((const float4*)g_rbuf)[(size_t)(2 * N_TOK * DIM / 4) + i4];
    float4 o;
    o.x = c.x + w0 * a.x + w1 * b.x;
    o.y = c.y + w0 * a.y + w1 * b.y;
    o.z = c.z + w0 * a.z + w1 * b.z;
    o.w = c.w + w0 * a.w + w1 * b.w;
    ((float4*)out)[i4] = o;
}

// ---------------- launch ----------------------------------------------------
extern "C" void kernel_launch(void* const* d_in, const int* in_sizes, int n_in,
                              void* d_out, int out_size)
{
    const float* x  = (const float*)d_in[0];
    const float* sg = (const float*)d_in[1];
    const float* su = (const float*)d_in[2];
    const float* sd = (const float*)d_in[3];
    const float* Wg = (const float*)d_in[4];
    const float* Wu = (const float*)d_in[5];
    const float* Wd = (const float*)d_in[6];
    const float* Wr = (const float*)d_in[7];
    const float* lt = (const float*)d_in[8];
    const int*   li = (const int*)d_in[9];
    float* out = (float*)d_out;
    (void)in_sizes; (void)n_in; (void)out_size;

    static int attr_done = 0;
    if (!attr_done) {
        cudaFuncSetAttribute(gemm1_kernel, cudaFuncAttributeMaxDynamicSharedMemorySize, 3 * Q1_STG);
        cudaFuncSetAttribute(gemm2_kernel, cudaFuncAttributeMaxDynamicSharedMemorySize, 3 * Q2_STG);
        attr_done = 1;
    }

    zero_kernel<<<1, 32>>>();
    quant_x_kernel<<<N_TOK / 8, 256>>>(x);
    colmax_kernel<<<dim3(4, 27), 256>>>(Wg, Wu, Wd, sg, su, sd);
    quant_w_kernel<<<dim3(32, 32, 27), dim3(32, 32)>>>(Wg, Wu, Wd, sg, su, sd);
    router_kernel<<<N_TOK / 32, 256>>>(x, Wr, lt, li);
    dispatch_kernel<<<N_TOK / 256, 256>>>();

    gemm1_kernel<<<dim3(HID / 64, N_TOK / 128, NSEG), 256, 3 * Q1_STG>>>();
    quant_h_kernel<<<NSEG * N_TOK / 8, 256>>>();
    gemm2_kernel<<<dim3(DIM / 128, N_TOK / 128, NSEG), 256, 3 * Q2_STG>>>();
    combine_kernel<<<(N_TOK * (DIM / 4)) / 256, 256>>>(out);
}

// round 6
// speedup vs baseline: 1.1483x; 1.1483x over previous
#include <cuda_runtime.h>
#include <cstdint>

#define N_TOK 4096
#define DIM   1024
#define HID   1024
#define NE    8
#define NSEG  9

// ---------------- scratch ---------------------------------------------------
__device__ int    g_cnt[NSEG];
__device__ int    g_assign_token[NE * N_TOK];
__device__ int    g_assign_slot [NE * N_TOK];
__device__ int    g_top_e[N_TOK * 2];
__device__ float  g_top_w[N_TOK * 2];
__device__ int8_t g_Xq1[(size_t)N_TOK * DIM];
__device__ int8_t g_Xq2[(size_t)N_TOK * DIM];
__device__ float  g_sX[N_TOK];
// 27 matrices [n][k]: Wg[0..7], Wu[8..15], Wd[16..23], sg=24, su=25, sd=26
__device__ int8_t g_Wq1[(size_t)27 * DIM * HID];
__device__ int8_t g_Wq2[(size_t)27 * DIM * HID];
__device__ float  g_sW[27 * 1024];
__device__ float  g_gate[(size_t)NSEG * N_TOK * HID];
__device__ float  g_up  [(size_t)NSEG * N_TOK * HID];
__device__ int8_t g_Hq1[(size_t)NSEG * N_TOK * HID];
__device__ int8_t g_Hq2[(size_t)NSEG * N_TOK * HID];
__device__ float  g_sH[NSEG * N_TOK];
__device__ float  g_rbuf[(size_t)3 * N_TOK * DIM];

// ---------------- helpers ---------------------------------------------------
__device__ __forceinline__ uint32_t smem_u32(const void* p) {
    uint32_t a;
    asm("{ .reg .u64 t; cvta.to.shared.u64 t, %1; cvt.u32.u64 %0, t; }"
        : "=r"(a) : "l"(p));
    return a;
}
#define CP_ASYNC16(dst, src) \
    asm volatile("cp.async.cg.shared.global [%0], [%1], 16;" :: "r"(dst), "l"(src))
#define CP_COMMIT() asm volatile("cp.async.commit_group;" ::: "memory")
#define CP_WAIT(n)  asm volatile("cp.async.wait_group %0;" :: "n"(n) : "memory")

__device__ __forceinline__ void ldsm_x4(uint32_t* r, uint32_t addr) {
    asm volatile("ldmatrix.sync.aligned.m8n8.x4.shared.b16 {%0,%1,%2,%3}, [%4];"
        : "=r"(r[0]), "=r"(r[1]), "=r"(r[2]), "=r"(r[3]) : "r"(addr));
}
__device__ __forceinline__ void ldsm_x2(uint32_t* r, uint32_t addr) {
    asm volatile("ldmatrix.sync.aligned.m8n8.x2.shared.b16 {%0,%1}, [%2];"
        : "=r"(r[0]), "=r"(r[1]) : "r"(addr));
}
__device__ __forceinline__ void mma_s8(int* d, const uint32_t* a, const uint32_t* b) {
    asm volatile(
        "mma.sync.aligned.m16n8k32.row.col.s32.s8.s8.s32 "
        "{%0,%1,%2,%3}, {%4,%5,%6,%7}, {%8,%9}, {%0,%1,%2,%3};"
        : "+r"(d[0]), "+r"(d[1]), "+r"(d[2]), "+r"(d[3])
        : "r"(a[0]), "r"(a[1]), "r"(a[2]), "r"(a[3]), "r"(b[0]), "r"(b[1]));
}
__device__ __forceinline__ float silu(float g) { return g / (1.f + __expf(-g)); }

__device__ __forceinline__ void q1(float v, float inv, int& a1, int& a2) {
    float q = v * inv;
    a1 = __float2int_rn(q);
    float r = q - (float)a1;
    a2 = __float2int_rn(r * 256.f);
    a2 = max(-127, min(127, a2));
}
__device__ __forceinline__ void q4pack(float4 v, float inv, uint32_t& o1, uint32_t& o2) {
    int a1x, a2x, a1y, a2y, a1z, a2z, a1w, a2w;
    q1(v.x, inv, a1x, a2x); q1(v.y, inv, a1y, a2y);
    q1(v.z, inv, a1z, a2z); q1(v.w, inv, a1w, a2w);
    o1 = (a1x & 255) | ((a1y & 255) << 8) | ((a1z & 255) << 16) | ((a1w & 255) << 24);
    o2 = (a2x & 255) | ((a2y & 255) << 8) | ((a2z & 255) << 16) | ((a2w & 255) << 24);
}

__device__ __forceinline__ const float* pick_src(
    int m, const float* Wg, const float* Wu, const float* Wd,
    const float* sg, const float* su, const float* sd)
{
    if (m < 8)  return Wg + (size_t)m * DIM * HID;
    if (m < 16) return Wu + (size_t)(m - 8) * DIM * HID;
    if (m < 24) return Wd + (size_t)(m - 16) * DIM * HID;
    if (m == 24) return sg;
    if (m == 25) return su;
    return sd;
}

// ---------------- small kernels ---------------------------------------------
__global__ void zero_kernel() {
    int t = threadIdx.x;
    if (t < NE) g_cnt[t] = 0;
    if (t == NE) g_cnt[NE] = N_TOK;
}

__global__ __launch_bounds__(256) void quant_x_kernel(const float* __restrict__ X) {
    const int warp = threadIdx.x >> 5, lane = threadIdx.x & 31;
    const int t = blockIdx.x * 8 + warp;
    const float4* xr = (const float4*)(X + (size_t)t * DIM);
    float4 xv[8];
    float mx = 0.f;
    #pragma unroll
    for (int i = 0; i < 8; i++) {
        xv[i] = xr[lane + 32 * i];
        mx = fmaxf(mx, fmaxf(fmaxf(fabsf(xv[i].x), fabsf(xv[i].y)),
                             fmaxf(fabsf(xv[i].z), fabsf(xv[i].w))));
    }
    #pragma unroll
    for (int o = 16; o; o >>= 1) mx = fmaxf(mx, __shfl_xor_sync(~0u, mx, o));
    mx = fmaxf(mx, 1e-30f);
    const float s = mx / 127.f, inv = 127.f / mx;
    uint32_t* r1 = (uint32_t*)(g_Xq1 + (size_t)t * DIM);
    uint32_t* r2 = (uint32_t*)(g_Xq2 + (size_t)t * DIM);
    #pragma unroll
    for (int i = 0; i < 8; i++) {
        uint32_t o1, o2;
        q4pack(xv[i], inv, o1, o2);
        r1[lane + 32 * i] = o1;
        r2[lane + 32 * i] = o2;
    }
    if (lane == 0) g_sX[t] = s;
}

__global__ void colmax_kernel(
    const float* __restrict__ Wg, const float* __restrict__ Wu,
    const float* __restrict__ Wd, const float* __restrict__ sg,
    const float* __restrict__ su, const float* __restrict__ sd)
{
    const int m = blockIdx.y;
    const float* src = pick_src(m, Wg, Wu, Wd, sg, su, sd);
    const int n = blockIdx.x * 256 + threadIdx.x;
    float mx = 0.f;
    #pragma unroll 8
    for (int k = 0; k < 1024; k++)
        mx = fmaxf(mx, fabsf(src[(size_t)k * 1024 + n]));
    g_sW[m * 1024 + n] = fmaxf(mx, 1e-30f) / 127.f;
}

// transpose+quantize: 64k x 32n tile, vectorized uint2 writes
__global__ __launch_bounds__(256) void quant_w_kernel(
    const float* __restrict__ Wg, const float* __restrict__ Wu,
    const float* __restrict__ Wd, const float* __restrict__ sg,
    const float* __restrict__ su, const float* __restrict__ sd)
{
    __shared__ float tb[64][33];
    const int m = blockIdx.z;
    const float* src = pick_src(m, Wg, Wu, Wd, sg, su, sd);
    const int kt = blockIdx.x * 64, nt = blockIdx.y * 32;
    for (int idx = threadIdx.x; idx < 64 * 32; idx += 256) {
        int r = idx >> 5, c = idx & 31;
        tb[r][c] = src[(size_t)(kt + r) * 1024 + nt + c];
    }
    __syncthreads();
    const int n = threadIdx.x >> 3, kq = threadIdx.x & 7;
    const float inv = 1.f / g_sW[m * 1024 + nt + n];
    uint32_t p1[2] = {0, 0}, p2[2] = {0, 0};
    #pragma unroll
    for (int t = 0; t < 8; t++) {
        int a1, a2;
        q1(tb[kq * 8 + t][n], inv, a1, a2);
        p1[t >> 2] |= (uint32_t)(a1 & 255) << ((t & 3) * 8);
        p2[t >> 2] |= (uint32_t)(a2 & 255) << ((t & 3) * 8);
    }
    size_t o = (size_t)m * (DIM * HID) + (size_t)(nt + n) * 1024 + kt + kq * 8;
    *(uint2*)(g_Wq1 + o) = make_uint2(p1[0], p1[1]);
    *(uint2*)(g_Wq2 + o) = make_uint2(p2[0], p2[1]);
}

__global__ __launch_bounds__(256) void router_kernel(
    const float* __restrict__ X, const float* __restrict__ Wr,
    const float* __restrict__ loop_table, const int* __restrict__ loop_idx)
{
    __shared__ float4 sW[NE][256];
    __shared__ float s_bias[NE];
    const int tid = threadIdx.x, warp = tid >> 5, lane = tid & 31;

    for (int i = tid; i < NE * 256; i += 256) {
        int e = i >> 8, k4 = i & 255;
        sW[e][k4] = make_float4(Wr[(size_t)(k4 * 4 + 0) * NE + e],
                                Wr[(size_t)(k4 * 4 + 1) * NE + e],
                                Wr[(size_t)(k4 * 4 + 2) * NE + e],
                                Wr[(size_t)(k4 * 4 + 3) * NE + e]);
    }
    const float* le = loop_table + (size_t)loop_idx[0] * DIM;
    float b = 0.f;
    for (int d = lane; d < DIM; d += 32)
        b += le[d] * Wr[(size_t)(DIM + d) * NE + warp];
    #pragma unroll
    for (int o = 16; o; o >>= 1) b += __shfl_xor_sync(~0u, b, o);
    if (lane == 0) s_bias[warp] = b;
    __syncthreads();

    #pragma unroll 1
    for (int rep = 0; rep < 4; rep++) {
        const int t = blockIdx.x * 32 + warp * 4 + rep;
        const float4* xr = (const float4*)(X + (size_t)t * DIM);
        float4 xv[8];
        #pragma unroll
        for (int i = 0; i < 8; i++) xv[i] = xr[lane + 32 * i];
        float acc[NE];
        #pragma unroll
        for (int e = 0; e < NE; e++) {
            float a = 0.f;
            #pragma unroll
            for (int i = 0; i < 8; i++) {
                float4 w = sW[e][lane + 32 * i];
                a += xv[i].x * w.x + xv[i].y * w.y + xv[i].z * w.z + xv[i].w * w.w;
            }
            acc[e] = a;
        }
        #pragma unroll
        for (int e = 0; e < NE; e++)
            #pragma unroll
            for (int o = 16; o; o >>= 1) acc[e] += __shfl_xor_sync(~0u, acc[e], o);

        if (lane == 0) {
            float p[NE];
            #pragma unroll
            for (int e = 0; e < NE; e++)
                p[e] = 1.f / (1.f + expf(-(acc[e] + s_bias[e])));
            int i0 = 0; float v0 = p[0];
            #pragma unroll
            for (int e = 1; e < NE; e++) if (p[e] > v0) { v0 = p[e]; i0 = e; }
            int i1 = -1; float v1 = -1e30f;
            #pragma unroll
            for (int e = 0; e < NE; e++) {
                if (e == i0) continue;
                if (p[e] > v1) { v1 = p[e]; i1 = e; }
            }
            g_top_e[t * 2 + 0] = i0;  g_top_e[t * 2 + 1] = i1;
            g_top_w[t * 2 + 0] = v0;  g_top_w[t * 2 + 1] = v1;
        }
    }
}

__global__ void dispatch_kernel() {
    int t = blockIdx.x * blockDim.x + threadIdx.x;
    if (t >= N_TOK) return;
    #pragma unroll
    for (int k = 0; k < 2; k++) {
        int e = g_top_e[t * 2 + k];
        int pos = atomicAdd(&g_cnt[e], 1);
        g_assign_token[e * N_TOK + pos] = t;
        g_assign_slot [e * N_TOK + pos] = k;
    }
}

// ---------------- shared GEMM smem layout -----------------------------------
#define Q_A1 0u
#define Q_A2 6144u
#define Q_B1 12288u
#define Q_B2 15360u
#define Q_STG 18432u

// ---------------- GEMM1: Xq @ Wg[e] or Wu[e] -> fp32 gate/up ----------------
// grid.x: 0..15 gate n-tiles, 16..31 up n-tiles. Block 128m x 64n.
__global__ __launch_bounds__(256) void gemm1_kernel() {
    extern __shared__ char sm[];
    __shared__ int   s_token[128];
    __shared__ float s_sx[128], s_sw[64];

    const int e   = blockIdx.z;
    const int cnt = g_cnt[e];
    const int m0  = blockIdx.y * 128;
    if (m0 >= cnt) return;
    const bool isU = blockIdx.x >= 16;
    const int n0  = (blockIdx.x & 15) * 64;
    const int tid = threadIdx.x, wid = tid >> 5, lane = tid & 31;

    const int imat = isU ? ((e < NE) ? 8 + e : 25) : ((e < NE) ? e : 24);

    if (tid < 128) {
        int r = m0 + tid;
        int tok = (e < NE) ? ((r < cnt) ? g_assign_token[e * N_TOK + r] : 0) : r;
        s_token[tid] = tok;
        s_sx[tid] = g_sX[tok];
    } else if (tid < 192) {
        s_sw[tid - 128] = g_sW[imat * 1024 + n0 + tid - 128];
    }
    __syncthreads();
    const uint32_t sb = smem_u32(sm);

    const int arow = tid >> 1, ahalf = tid & 1;
    const char* aSrc1 = (const char*)(g_Xq1 + (size_t)s_token[arow] * DIM) + ahalf * 16;
    const char* aSrc2 = (const char*)(g_Xq2 + (size_t)s_token[arow] * DIM) + ahalf * 16;
    const uint32_t aDst1 = sb + Q_A1 + arow * 48 + ahalf * 16;
    const uint32_t aDst2 = sb + Q_A2 + arow * 48 + ahalf * 16;
    const int brow = (tid & 127) >> 1, bhalf = tid & 1;
    const bool sl1 = tid < 128;
    const char* bSrc = (const char*)((sl1 ? g_Wq1 : g_Wq2) + (size_t)imat * DIM * HID
                                     + (size_t)(n0 + brow) * 1024) + bhalf * 16;
    const uint32_t bDst = sb + (sl1 ? Q_B1 : Q_B2) + brow * 48 + bhalf * 16;

#define Q1_LOAD(k0, buf) do { \
        uint32_t _o = (uint32_t)(buf) * Q_STG; \
        CP_ASYNC16(aDst1 + _o, aSrc1 + (k0)); \
        CP_ASYNC16(aDst2 + _o, aSrc2 + (k0)); \
        CP_ASYNC16(bDst + _o, bSrc + (k0)); \
        CP_COMMIT(); } while (0)

    const int wm = (wid & 3) * 32, wn = (wid >> 2) * 32;
    const uint32_t aB1 = sb + Q_A1 + (wm + (lane & 15)) * 48 + (lane >> 4) * 16;
    const uint32_t aB2 = sb + Q_A2 + (wm + (lane & 15)) * 48 + (lane >> 4) * 16;
    const uint32_t bOff = (wn + (lane & 7)) * 48 + ((lane >> 3) & 1) * 16;
    const uint32_t bB1 = sb + Q_B1 + bOff;
    const uint32_t bB2 = sb + Q_B2 + bOff;

    int acc1[2][4][4], acc2[2][4][4];
    #pragma unroll
    for (int i = 0; i < 2; i++)
        #pragma unroll
        for (int j = 0; j < 4; j++)
            #pragma unroll
            for (int q = 0; q < 4; q++) { acc1[i][j][q] = 0; acc2[i][j][q] = 0; }

    Q1_LOAD(0, 0);
    Q1_LOAD(32, 1);
    CP_WAIT(1); __syncthreads();

    int cur = 0;
    for (int s = 0; s < 32; s++) {
        int ldb = cur + 2; if (ldb >= 3) ldb -= 3;
        if (s + 2 < 32) Q1_LOAD((s + 2) * 32, ldb);

        const uint32_t off = (uint32_t)cur * Q_STG;
        uint32_t a1[2][4], a2[2][4], b1[4][2], b2[4][2];
        #pragma unroll
        for (int i = 0; i < 2; i++) {
            ldsm_x4(a1[i], aB1 + off + i * 768);
            ldsm_x4(a2[i], aB2 + off + i * 768);
        }
        #pragma unroll
        for (int j = 0; j < 4; j++) {
            ldsm_x2(b1[j], bB1 + off + j * 384);
            ldsm_x2(b2[j], bB2 + off + j * 384);
        }
        #pragma unroll
        for (int i = 0; i < 2; i++)
            #pragma unroll
            for (int j = 0; j < 4; j++) {
                mma_s8(acc1[i][j], a1[i], b1[j]);
                mma_s8(acc2[i][j], a1[i], b2[j]);
                mma_s8(acc2[i][j], a2[i], b1[j]);
            }
        if (s + 2 < 32) CP_WAIT(1); else CP_WAIT(0);
        __syncthreads();
        cur++; if (cur == 3) cur = 0;
    }

    float* OutBuf = isU ? g_up : g_gate;
    const float inv256 = 1.f / 256.f;
    const int qr = lane >> 2, r4 = lane & 3;
    #pragma unroll
    for (int i = 0; i < 2; i++) {
        const int lr0 = wm + i * 16 + qr, lr1 = lr0 + 8;
        const bool ok0 = (m0 + lr0) < cnt, ok1 = (m0 + lr1) < cnt;
        const float sx0 = s_sx[lr0], sx1 = s_sx[lr1];
        float* d0 = OutBuf + ((size_t)e * N_TOK + m0 + lr0) * HID + n0;
        float* d1 = OutBuf + ((size_t)e * N_TOK + m0 + lr1) * HID + n0;
        #pragma unroll
        for (int j = 0; j < 4; j++) {
            const int col = wn + j * 8 + r4 * 2;
            const float sw0 = s_sw[col], sw1 = s_sw[col + 1];
            float c00 = sx0 * sw0 * ((float)acc1[i][j][0] + (float)acc2[i][j][0] * inv256);
            float c01 = sx0 * sw1 * ((float)acc1[i][j][1] + (float)acc2[i][j][1] * inv256);
            float c10 = sx1 * sw0 * ((float)acc1[i][j][2] + (float)acc2[i][j][2] * inv256);
            float c11 = sx1 * sw1 * ((float)acc1[i][j][3] + (float)acc2[i][j][3] * inv256);
            if (ok0) *(float2*)(d0 + col) = make_float2(c00, c01);
            if (ok1) *(float2*)(d1 + col) = make_float2(c10, c11);
        }
    }
#undef Q1_LOAD
}

// ---------------- act+quant: h = silu(gate)*up -> 2-slice s8 ----------------
__global__ __launch_bounds__(256) void act_quant_kernel() {
    const int warp = threadIdx.x >> 5, lane = threadIdx.x & 31;
    const int row = blockIdx.x * 8 + warp;
    const int e = row >> 12, r = row & (N_TOK - 1);
    if (r >= g_cnt[e]) return;
    const float4* gp = (const float4*)(g_gate + (size_t)row * HID);
    const float4* up = (const float4*)(g_up   + (size_t)row * HID);
    float4 hv[8];
    float mx = 0.f;
    #pragma unroll
    for (int i = 0; i < 8; i++) {
        float4 g = gp[lane + 32 * i];
        float4 u = up[lane + 32 * i];
        hv[i].x = silu(g.x) * u.x;
        hv[i].y = silu(g.y) * u.y;
        hv[i].z = silu(g.z) * u.z;
        hv[i].w = silu(g.w) * u.w;
        mx = fmaxf(mx, fmaxf(fmaxf(fabsf(hv[i].x), fabsf(hv[i].y)),
                             fmaxf(fabsf(hv[i].z), fabsf(hv[i].w))));
    }
    #pragma unroll
    for (int o = 16; o; o >>= 1) mx = fmaxf(mx, __shfl_xor_sync(~0u, mx, o));
    mx = fmaxf(mx, 1e-30f);
    const float s = mx / 127.f, inv = 127.f / mx;
    uint32_t* r1 = (uint32_t*)(g_Hq1 + (size_t)row * HID);
    uint32_t* r2 = (uint32_t*)(g_Hq2 + (size_t)row * HID);
    #pragma unroll
    for (int i = 0; i < 8; i++) {
        uint32_t o1, o2;
        q4pack(hv[i], inv, o1, o2);
        r1[lane + 32 * i] = o1;
        r2[lane + 32 * i] = o2;
    }
    if (lane == 0) g_sH[row] = s;
}

// ---------------- GEMM2: Hq @ Wd[e] -> scattered fp32 rbuf ------------------
// Block 128m x 64n.
__global__ __launch_bounds__(256) void gemm2_kernel() {
    extern __shared__ char sm[];
    __shared__ int   s_dst[128];
    __shared__ float s_sh[128], s_sd[64];

    const int e   = blockIdx.z;
    const int cnt = g_cnt[e];
    const int m0  = blockIdx.y * 128;
    if (m0 >= cnt) return;
    const int n0  = blockIdx.x * 64;
    const int tid = threadIdx.x, wid = tid >> 5, lane = tid & 31;

    const int id = (e < NE) ? 16 + e : 26;

    if (tid < 128) {
        int r = m0 + tid, dst = 0;
        if (r < cnt) {
            if (e < NE)
                dst = g_assign_slot[e * N_TOK + r] * N_TOK + g_assign_token[e * N_TOK + r];
            else
                dst = 2 * N_TOK + r;
        }
        s_dst[tid] = dst;
        s_sh[tid] = g_sH[e * N_TOK + m0 + tid];
    } else if (tid < 192) {
        s_sd[tid - 128] = g_sW[id * 1024 + n0 + tid - 128];
    }
    __syncthreads();
    const uint32_t sb = smem_u32(sm);

    const int arow = tid >> 1, ahalf = tid & 1;
    const char* aSrc1 = (const char*)(g_Hq1 + ((size_t)e * N_TOK + m0 + arow) * HID) + ahalf * 16;
    const char* aSrc2 = (const char*)(g_Hq2 + ((size_t)e * N_TOK + m0 + arow) * HID) + ahalf * 16;
    const uint32_t aDst1 = sb + Q_A1 + arow * 48 + ahalf * 16;
    const uint32_t aDst2 = sb + Q_A2 + arow * 48 + ahalf * 16;
    const int brow = (tid & 127) >> 1, bhalf = tid & 1;
    const bool sl1 = tid < 128;
    const char* bSrc = (const char*)((sl1 ? g_Wq1 : g_Wq2) + (size_t)id * DIM * HID
                                     + (size_t)(n0 + brow) * 1024) + bhalf * 16;
    const uint32_t bDst = sb + (sl1 ? Q_B1 : Q_B2) + brow * 48 + bhalf * 16;

#define Q2_LOAD(k0, buf) do { \
        uint32_t _o = (uint32_t)(buf) * Q_STG; \
        CP_ASYNC16(aDst1 + _o, aSrc1 + (k0)); \
        CP_ASYNC16(aDst2 + _o, aSrc2 + (k0)); \
        CP_ASYNC16(bDst + _o, bSrc + (k0)); \
        CP_COMMIT(); } while (0)

    const int wm = (wid & 3) * 32, wn = (wid >> 2) * 32;
    const uint32_t aB1 = sb + Q_A1 + (wm + (lane & 15)) * 48 + (lane >> 4) * 16;
    const uint32_t aB2 = sb + Q_A2 + (wm + (lane & 15)) * 48 + (lane >> 4) * 16;
    const uint32_t bOff = (wn + (lane & 7)) * 48 + ((lane >> 3) & 1) * 16;
    const uint32_t bB1 = sb + Q_B1 + bOff;
    const uint32_t bB2 = sb + Q_B2 + bOff;

    int acc1[2][4][4], acc2[2][4][4];
    #pragma unroll
    for (int i = 0; i < 2; i++)
        #pragma unroll
        for (int j = 0; j < 4; j++)
            #pragma unroll
            for (int q = 0; q < 4; q++) { acc1[i][j][q] = 0; acc2[i][j][q] = 0; }

    Q2_LOAD(0, 0);
    Q2_LOAD(32, 1);
    CP_WAIT(1); __syncthreads();

    int cur = 0;
    for (int s = 0; s < 32; s++) {
        int ldb = cur + 2; if (ldb >= 3) ldb -= 3;
        if (s + 2 < 32) Q2_LOAD((s + 2) * 32, ldb);

        const uint32_t off = (uint32_t)cur * Q_STG;
        uint32_t a1[2][4], a2[2][4], b1[4][2], b2[4][2];
        #pragma unroll
        for (int i = 0; i < 2; i++) {
            ldsm_x4(a1[i], aB1 + off + i * 768);
            ldsm_x4(a2[i], aB2 + off + i * 768);
        }
        #pragma unroll
        for (int j = 0; j < 4; j++) {
            ldsm_x2(b1[j], bB1 + off + j * 384);
            ldsm_x2(b2[j], bB2 + off + j * 384);
        }
        #pragma unroll
        for (int i = 0; i < 2; i++)
            #pragma unroll
            for (int j = 0; j < 4; j++) {
                mma_s8(acc1[i][j], a1[i], b1[j]);
                mma_s8(acc2[i][j], a1[i], b2[j]);
                mma_s8(acc2[i][j], a2[i], b1[j]);
            }
        if (s + 2 < 32) CP_WAIT(1); else CP_WAIT(0);
        __syncthreads();
        cur++; if (cur == 3) cur = 0;
    }

    const float inv256 = 1.f / 256.f;
    const int qr = lane >> 2, r4 = lane & 3;
    #pragma unroll
    for (int i = 0; i < 2; i++) {
        const int lr0 = wm + i * 16 + qr, lr1 = lr0 + 8;
        const bool ok0 = (m0 + lr0) < cnt, ok1 = (m0 + lr1) < cnt;
        const float sh0 = s_sh[lr0], sh1 = s_sh[lr1];
        float* d0 = g_rbuf + (size_t)s_dst[lr0] * DIM + n0;
        float* d1 = g_rbuf + (size_t)s_dst[lr1] * DIM + n0;
        #pragma unroll
        for (int j = 0; j < 4; j++) {
            const int col = wn + j * 8 + r4 * 2;
            const float sd0 = s_sd[col], sd1 = s_sd[col + 1];
            float c00 = sh0 * sd0 * ((float)acc1[i][j][0] + (float)acc2[i][j][0] * inv256);
            float c01 = sh0 * sd1 * ((float)acc1[i][j][1] + (float)acc2[i][j][1] * inv256);
            float c10 = sh1 * sd0 * ((float)acc1[i][j][2] + (float)acc2[i][j][2] * inv256);
            float c11 = sh1 * sd1 * ((float)acc1[i][j][3] + (float)acc2[i][j][3] * inv256);
            if (ok0) *(float2*)(d0 + col) = make_float2(c00, c01);
            if (ok1) *(float2*)(d1 + col) = make_float2(c10, c11);
        }
    }
#undef Q2_LOAD
}

// ---------------- combine ---------------------------------------------------
__global__ void combine_kernel(float* __restrict__ out) {
    int i4 = blockIdx.x * 256 + threadIdx.x;
    int t  = i4 >> 8;
    float w0 = g_top_w[2 * t], w1 = g_top_w[2 * t + 1];
    float4 a = ((const float4*)g_rbuf)[i4];
    float4 b = ((const float4*)g_rbuf)[(size_t)(N_TOK * DIM / 4) + i4];
    float4 c = ((const float4*)g_rbuf)[(size_t)(2 * N_TOK * DIM / 4) + i4];
    float4 o;
    o.x = c.x + w0 * a.x + w1 * b.x;
    o.y = c.y + w0 * a.y + w1 * b.y;
    o.z = c.z + w0 * a.z + w1 * b.z;
    o.w = c.w + w0 * a.w + w1 * b.w;
    ((float4*)out)[i4] = o;
}

// ---------------- launch ----------------------------------------------------
extern "C" void kernel_launch(void* const* d_in, const int* in_sizes, int n_in,
                              void* d_out, int out_size)
{
    const float* x  = (const float*)d_in[0];
    const float* sg = (const float*)d_in[1];
    const float* su = (const float*)d_in[2];
    const float* sd = (const float*)d_in[3];
    const float* Wg = (const float*)d_in[4];
    const float* Wu = (const float*)d_in[5];
    const float* Wd = (const float*)d_in[6];
    const float* Wr = (const float*)d_in[7];
    const float* lt = (const float*)d_in[8];
    const int*   li = (const int*)d_in[9];
    float* out = (float*)d_out;
    (void)in_sizes; (void)n_in; (void)out_size;

    static int attr_done = 0;
    if (!attr_done) {
        cudaFuncSetAttribute(gemm1_kernel, cudaFuncAttributeMaxDynamicSharedMemorySize, 3 * Q_STG);
        cudaFuncSetAttribute(gemm2_kernel, cudaFuncAttributeMaxDynamicSharedMemorySize, 3 * Q_STG);
        attr_done = 1;
    }

    zero_kernel<<<1, 32>>>();
    quant_x_kernel<<<N_TOK / 8, 256>>>(x);
    colmax_kernel<<<dim3(4, 27), 256>>>(Wg, Wu, Wd, sg, su, sd);
    quant_w_kernel<<<dim3(16, 32, 27), 256>>>(Wg, Wu, Wd, sg, su, sd);
    router_kernel<<<N_TOK / 32, 256>>>(x, Wr, lt, li);
    dispatch_kernel<<<N_TOK / 256, 256>>>();

    gemm1_kernel<<<dim3(32, 32, NSEG), 256, 3 * Q_STG>>>();
    act_quant_kernel<<<NSEG * N_TOK / 8, 256>>>();
    gemm2_kernel<<<dim3(16, 32, NSEG), 256, 3 * Q_STG>>>();
    combine_kernel<<<(N_TOK * (DIM / 4)) / 256, 256>>>(out);
}

// round 7
// speedup vs baseline: 2.3498x; 2.0463x over previous
#include <cuda_runtime.h>
#include <cuda_bf16.h>
#include <cstdint>

#define N_TOK 4096
#define DIM   1024
#define HID   1024
#define NE    8
#define NSEG  9

// ---------------- scratch ---------------------------------------------------
__device__ int   g_cnt[NSEG];
__device__ int   g_assign_token[NE * N_TOK];
__device__ int   g_assign_slot [NE * N_TOK];
__device__ int   g_top_e[N_TOK * 2];
__device__ float g_top_w[N_TOK * 2];
__device__ __nv_bfloat16 g_Xh[(size_t)N_TOK * DIM];
__device__ __nv_bfloat16 g_Xl[(size_t)N_TOK * DIM];
// 27 matrices [k][n]: Wg[0..7], Wu[8..15], Wd[16..23], sg=24, su=25, sd=26
__device__ __nv_bfloat16 g_Wh[(size_t)27 * DIM * HID];
__device__ __nv_bfloat16 g_Wl[(size_t)27 * DIM * HID];
__device__ float g_gate[(size_t)NSEG * N_TOK * HID];
__device__ float g_up  [(size_t)NSEG * N_TOK * HID];
__device__ __nv_bfloat16 g_hh[(size_t)NSEG * N_TOK * HID];
__device__ __nv_bfloat16 g_hl[(size_t)NSEG * N_TOK * HID];
__device__ float g_rbuf[(size_t)3 * N_TOK * DIM];

// ---------------- helpers ---------------------------------------------------
__device__ __forceinline__ uint32_t smem_u32(const void* p) {
    uint32_t a;
    asm("{ .reg .u64 t; cvta.to.shared.u64 t, %1; cvt.u32.u64 %0, t; }"
        : "=r"(a) : "l"(p));
    return a;
}
#define CP_ASYNC16(dst, src) \
    asm volatile("cp.async.cg.shared.global [%0], [%1], 16;" :: "r"(dst), "l"(src))
#define CP_COMMIT() asm volatile("cp.async.commit_group;" ::: "memory")
#define CP_WAIT(n)  asm volatile("cp.async.wait_group %0;" :: "n"(n) : "memory")

__device__ __forceinline__ void ldsm_x4(uint32_t* r, uint32_t addr) {
    asm volatile("ldmatrix.sync.aligned.m8n8.x4.shared.b16 {%0,%1,%2,%3}, [%4];"
        : "=r"(r[0]), "=r"(r[1]), "=r"(r[2]), "=r"(r[3]) : "r"(addr));
}
__device__ __forceinline__ void ldsm_x2_t(uint32_t* r, uint32_t addr) {
    asm volatile("ldmatrix.sync.aligned.m8n8.x2.trans.shared.b16 {%0,%1}, [%2];"
        : "=r"(r[0]), "=r"(r[1]) : "r"(addr));
}
__device__ __forceinline__ void mma_bf16(float* d, const uint32_t* a, const uint32_t* b) {
    asm volatile(
        "mma.sync.aligned.m16n8k16.row.col.f32.bf16.bf16.f32 "
        "{%0,%1,%2,%3}, {%4,%5,%6,%7}, {%8,%9}, {%0,%1,%2,%3};"
        : "+f"(d[0]), "+f"(d[1]), "+f"(d[2]), "+f"(d[3])
        : "r"(a[0]), "r"(a[1]), "r"(a[2]), "r"(a[3]), "r"(b[0]), "r"(b[1]));
}
__device__ __forceinline__ float silu(float g) { return g / (1.f + __expf(-g)); }

__device__ __forceinline__ const float* pick_src(
    int m, const float* Wg, const float* Wu, const float* Wd,
    const float* sg, const float* su, const float* sd)
{
    if (m < 8)  return Wg + (size_t)m * DIM * HID;
    if (m < 16) return Wu + (size_t)(m - 8) * DIM * HID;
    if (m < 24) return Wd + (size_t)(m - 16) * DIM * HID;
    if (m == 24) return sg;
    if (m == 25) return su;
    return sd;
}

// ---------------- small kernels ---------------------------------------------
__global__ void zero_kernel() {
    int t = threadIdx.x;
    if (t < NE) g_cnt[t] = 0;
    if (t == NE) g_cnt[NE] = N_TOK;
}

__global__ void convert_x_kernel(const float* __restrict__ x) {
    size_t i4 = (size_t)blockIdx.x * 256 + threadIdx.x;
    float4 v = ((const float4*)x)[i4];
    __nv_bfloat16 h0 = __float2bfloat16(v.x), h1 = __float2bfloat16(v.y);
    __nv_bfloat16 h2 = __float2bfloat16(v.z), h3 = __float2bfloat16(v.w);
    __nv_bfloat162 a, bq, c, d;
    a.x = h0; a.y = h1; bq.x = h2; bq.y = h3;
    c.x = __float2bfloat16(v.x - __bfloat162float(h0));
    c.y = __float2bfloat16(v.y - __bfloat162float(h1));
    d.x = __float2bfloat16(v.z - __bfloat162float(h2));
    d.y = __float2bfloat16(v.w - __bfloat162float(h3));
    ((uint2*)g_Xh)[i4] = make_uint2(*(uint32_t*)&a, *(uint32_t*)&bq);
    ((uint2*)g_Xl)[i4] = make_uint2(*(uint32_t*)&c, *(uint32_t*)&d);
}

__global__ void convert_w_kernel(
    const float* __restrict__ Wg, const float* __restrict__ Wu,
    const float* __restrict__ Wd, const float* __restrict__ sg,
    const float* __restrict__ su, const float* __restrict__ sd)
{
    int m = blockIdx.y;
    const float* src = pick_src(m, Wg, Wu, Wd, sg, su, sd);
    size_t i4 = (size_t)blockIdx.x * 256 + threadIdx.x;
    float4 v = ((const float4*)src)[i4];
    __nv_bfloat16 h0 = __float2bfloat16(v.x), h1 = __float2bfloat16(v.y);
    __nv_bfloat16 h2 = __float2bfloat16(v.z), h3 = __float2bfloat16(v.w);
    __nv_bfloat162 a, bq, c, d;
    a.x = h0; a.y = h1; bq.x = h2; bq.y = h3;
    c.x = __float2bfloat16(v.x - __bfloat162float(h0));
    c.y = __float2bfloat16(v.y - __bfloat162float(h1));
    d.x = __float2bfloat16(v.z - __bfloat162float(h2));
    d.y = __float2bfloat16(v.w - __bfloat162float(h3));
    size_t o = (size_t)m * (DIM * HID / 4) + i4;
    ((uint2*)g_Wh)[o] = make_uint2(*(uint32_t*)&a, *(uint32_t*)&bq);
    ((uint2*)g_Wl)[o] = make_uint2(*(uint32_t*)&c, *(uint32_t*)&d);
}

__global__ __launch_bounds__(256) void router_kernel(
    const float* __restrict__ X, const float* __restrict__ Wr,
    const float* __restrict__ loop_table, const int* __restrict__ loop_idx)
{
    __shared__ float4 sW[NE][256];
    __shared__ float s_bias[NE];
    const int tid = threadIdx.x, warp = tid >> 5, lane = tid & 31;

    for (int i = tid; i < NE * 256; i += 256) {
        int e = i >> 8, k4 = i & 255;
        sW[e][k4] = make_float4(Wr[(size_t)(k4 * 4 + 0) * NE + e],
                                Wr[(size_t)(k4 * 4 + 1) * NE + e],
                                Wr[(size_t)(k4 * 4 + 2) * NE + e],
                                Wr[(size_t)(k4 * 4 + 3) * NE + e]);
    }
    const float* le = loop_table + (size_t)loop_idx[0] * DIM;
    float b = 0.f;
    for (int d = lane; d < DIM; d += 32)
        b += le[d] * Wr[(size_t)(DIM + d) * NE + warp];
    #pragma unroll
    for (int o = 16; o; o >>= 1) b += __shfl_xor_sync(~0u, b, o);
    if (lane == 0) s_bias[warp] = b;
    __syncthreads();

    #pragma unroll 1
    for (int rep = 0; rep < 4; rep++) {
        const int t = blockIdx.x * 32 + warp * 4 + rep;
        const float4* xr = (const float4*)(X + (size_t)t * DIM);
        float4 xv[8];
        #pragma unroll
        for (int i = 0; i < 8; i++) xv[i] = xr[lane + 32 * i];
        float acc[NE];
        #pragma unroll
        for (int e = 0; e < NE; e++) {
            float a = 0.f;
            #pragma unroll
            for (int i = 0; i < 8; i++) {
                float4 w = sW[e][lane + 32 * i];
                a += xv[i].x * w.x + xv[i].y * w.y + xv[i].z * w.z + xv[i].w * w.w;
            }
            acc[e] = a;
        }
        #pragma unroll
        for (int e = 0; e < NE; e++)
            #pragma unroll
            for (int o = 16; o; o >>= 1) acc[e] += __shfl_xor_sync(~0u, acc[e], o);

        if (lane == 0) {
            float p[NE];
            #pragma unroll
            for (int e = 0; e < NE; e++)
                p[e] = 1.f / (1.f + expf(-(acc[e] + s_bias[e])));
            int i0 = 0; float v0 = p[0];
            #pragma unroll
            for (int e = 1; e < NE; e++) if (p[e] > v0) { v0 = p[e]; i0 = e; }
            int i1 = -1; float v1 = -1e30f;
            #pragma unroll
            for (int e = 0; e < NE; e++) {
                if (e == i0) continue;
                if (p[e] > v1) { v1 = p[e]; i1 = e; }
            }
            g_top_e[t * 2 + 0] = i0;  g_top_e[t * 2 + 1] = i1;
            g_top_w[t * 2 + 0] = v0;  g_top_w[t * 2 + 1] = v1;
        }
    }
}

__global__ void dispatch_kernel() {
    int t = blockIdx.x * blockDim.x + threadIdx.x;
    if (t >= N_TOK) return;
    #pragma unroll
    for (int k = 0; k < 2; k++) {
        int e = g_top_e[t * 2 + k];
        int pos = atomicAdd(&g_cnt[e], 1);
        g_assign_token[e * N_TOK + pos] = t;
        g_assign_slot [e * N_TOK + pos] = k;
    }
}

// ---------------- shared GEMM smem layout (per stage 16896 B) ---------------
#define S_AH 0u
#define S_AL 6144u
#define S_BH 12288u
#define S_BL 14592u
#define S_STG 16896u

// ---------------- GEMM1: X @ Wg[e] or Wu[e] -> fp32 gate/up -----------------
// grid.x 0..15 gate n-tiles, 16..31 up. Block 128m x 64n, warps 4m x 2n (32x32).
__global__ __launch_bounds__(256, 2) void gemm1_kernel() {
    extern __shared__ char sm[];
    __shared__ int s_token[128];

    const int e   = blockIdx.z;
    const int cnt = g_cnt[e];
    const int m0  = blockIdx.y * 128;
    if (m0 >= cnt) return;
    const bool isU = blockIdx.x >= 16;
    const int n0  = (blockIdx.x & 15) * 64;
    const int tid = threadIdx.x, wid = tid >> 5, lane = tid & 31;

    const int imat = isU ? ((e < NE) ? 8 + e : 25) : ((e < NE) ? e : 24);

    if (tid < 128) {
        int r = m0 + tid;
        s_token[tid] = (e < NE) ? ((r < cnt) ? g_assign_token[e * N_TOK + r] : 0) : r;
    }
    __syncthreads();
    const uint32_t sb = smem_u32(sm);

    const char* wh = (const char*)(g_Wh + (size_t)imat * DIM * HID);
    const char* wl = (const char*)(g_Wl + (size_t)imat * DIM * HID);

    const int ar = tid >> 1, ahalf = tid & 1;
    const char* aSrcH = (const char*)(g_Xh + (size_t)s_token[ar] * DIM) + ahalf * 16;
    const char* aSrcL = (const char*)(g_Xl + (size_t)s_token[ar] * DIM) + ahalf * 16;
    const uint32_t aDstH = sb + S_AH + ar * 48 + ahalf * 16;
    const uint32_t aDstL = sb + S_AL + ar * 48 + ahalf * 16;
    const int brow = (tid & 127) >> 3, bc = (tid & 7) * 16;
    const bool hi = tid < 128;
    const char* bSrc = (hi ? wh : wl) + (size_t)brow * HID * 2 + n0 * 2 + bc;
    const uint32_t bDst = sb + (hi ? S_BH : S_BL) + brow * 144 + bc;

#define G_LOAD(k0, buf) do { \
        uint32_t _o = (uint32_t)(buf) * S_STG; \
        size_t _bk = (size_t)(k0) * HID * 2; \
        CP_ASYNC16(aDstH + _o, aSrcH + (size_t)(k0) * 2); \
        CP_ASYNC16(aDstL + _o, aSrcL + (size_t)(k0) * 2); \
        CP_ASYNC16(bDst + _o, bSrc + _bk); \
        CP_COMMIT(); } while (0)

    const int wm = (wid & 3) * 32, wn = (wid >> 2) * 32;
    const int am = (lane & 7) + ((lane >> 3) & 1) * 8;
    const uint32_t ako = (lane >> 4) * 16;
    const uint32_t aBH = sb + S_AH + (wm + am) * 48 + ako;
    const uint32_t aBL = sb + S_AL + (wm + am) * 48 + ako;
    const int bk = lane & 15;
    const uint32_t bBH = sb + S_BH + bk * 144 + wn * 2;
    const uint32_t bBL = sb + S_BL + bk * 144 + wn * 2;

    float acc[2][4][4];
    #pragma unroll
    for (int i = 0; i < 2; i++)
        #pragma unroll
        for (int j = 0; j < 4; j++)
            #pragma unroll
            for (int q = 0; q < 4; q++) acc[i][j][q] = 0.f;

    G_LOAD(0, 0);
    G_LOAD(16, 1);
    CP_WAIT(1); __syncthreads();

    int cur = 0;
    for (int s = 0; s < 64; s++) {
        int ldb = cur + 2; if (ldb >= 3) ldb -= 3;
        if (s + 2 < 64) G_LOAD((s + 2) * 16, ldb);

        const uint32_t off = (uint32_t)cur * S_STG;
        uint32_t ah[2][4], al[2][4], bh[4][2], bl[4][2];
        #pragma unroll
        for (int i = 0; i < 2; i++) {
            ldsm_x4(ah[i], aBH + off + i * 768);
            ldsm_x4(al[i], aBL + off + i * 768);
        }
        #pragma unroll
        for (int j = 0; j < 4; j++) {
            ldsm_x2_t(bh[j], bBH + off + j * 16);
            ldsm_x2_t(bl[j], bBL + off + j * 16);
        }
        #pragma unroll
        for (int i = 0; i < 2; i++)
            #pragma unroll
            for (int j = 0; j < 4; j++) {
                mma_bf16(acc[i][j], ah[i], bh[j]);
                mma_bf16(acc[i][j], ah[i], bl[j]);
                mma_bf16(acc[i][j], al[i], bh[j]);
            }
        if (s + 2 < 64) CP_WAIT(1); else CP_WAIT(0);
        __syncthreads();
        cur++; if (cur == 3) cur = 0;
    }

    float* OutBuf = isU ? g_up : g_gate;
    const int qr = lane >> 2, r4 = lane & 3;
    #pragma unroll
    for (int i = 0; i < 2; i++) {
        const int lr0 = wm + i * 16 + qr, lr1 = lr0 + 8;
        const bool ok0 = (m0 + lr0) < cnt, ok1 = (m0 + lr1) < cnt;
        float* d0 = OutBuf + ((size_t)e * N_TOK + m0 + lr0) * HID + n0;
        float* d1 = OutBuf + ((size_t)e * N_TOK + m0 + lr1) * HID + n0;
        #pragma unroll
        for (int j = 0; j < 4; j++) {
            const int col = wn + j * 8 + r4 * 2;
            if (ok0) *(float2*)(d0 + col) = make_float2(acc[i][j][0], acc[i][j][1]);
            if (ok1) *(float2*)(d1 + col) = make_float2(acc[i][j][2], acc[i][j][3]);
        }
    }
#undef G_LOAD
}

// ---------------- act: h = silu(gate)*up -> bf16 hi/lo ----------------------
__global__ __launch_bounds__(256) void act_convert_kernel() {
    const int warp = threadIdx.x >> 5, lane = threadIdx.x & 31;
    const int row = blockIdx.x * 8 + warp;
    const int e = row >> 12, r = row & (N_TOK - 1);
    if (r >= g_cnt[e]) return;
    const float4* gp = (const float4*)(g_gate + (size_t)row * HID);
    const float4* up = (const float4*)(g_up   + (size_t)row * HID);
    uint2* hh = (uint2*)(g_hh + (size_t)row * HID);
    uint2* hl = (uint2*)(g_hl + (size_t)row * HID);
    #pragma unroll
    for (int i = 0; i < 8; i++) {
        float4 g = gp[lane + 32 * i];
        float4 u = up[lane + 32 * i];
        float h0 = silu(g.x) * u.x, h1 = silu(g.y) * u.y;
        float h2 = silu(g.z) * u.z, h3 = silu(g.w) * u.w;
        __nv_bfloat16 b0 = __float2bfloat16(h0), b1 = __float2bfloat16(h1);
        __nv_bfloat16 b2 = __float2bfloat16(h2), b3 = __float2bfloat16(h3);
        __nv_bfloat162 a, bq, c, d;
        a.x = b0; a.y = b1; bq.x = b2; bq.y = b3;
        c.x = __float2bfloat16(h0 - __bfloat162float(b0));
        c.y = __float2bfloat16(h1 - __bfloat162float(b1));
        d.x = __float2bfloat16(h2 - __bfloat162float(b2));
        d.y = __float2bfloat16(h3 - __bfloat162float(b3));
        hh[lane + 32 * i] = make_uint2(*(uint32_t*)&a, *(uint32_t*)&bq);
        hl[lane + 32 * i] = make_uint2(*(uint32_t*)&c, *(uint32_t*)&d);
    }
}

// ---------------- GEMM2: h @ Wd[e] -> scattered fp32 rbuf -------------------
// Block 128m x 64n, warps 4m x 2n.
__global__ __launch_bounds__(256, 2) void gemm2_kernel() {
    extern __shared__ char sm[];
    __shared__ int s_dst[128];

    const int e   = blockIdx.z;
    const int cnt = g_cnt[e];
    const int m0  = blockIdx.y * 128;
    if (m0 >= cnt) return;
    const int n0  = blockIdx.x * 64;
    const int tid = threadIdx.x, wid = tid >> 5, lane = tid & 31;

    const int id = (e < NE) ? 16 + e : 26;

    if (tid < 128) {
        int r = m0 + tid, dst = 0;
        if (r < cnt) {
            if (e < NE)
                dst = g_assign_slot[e * N_TOK + r] * N_TOK + g_assign_token[e * N_TOK + r];
            else
                dst = 2 * N_TOK + r;
        }
        s_dst[tid] = dst;
    }
    __syncthreads();
    const uint32_t sb = smem_u32(sm);

    const char* wh = (const char*)(g_Wh + (size_t)id * DIM * HID);
    const char* wl = (const char*)(g_Wl + (size_t)id * DIM * HID);

    const int ar = tid >> 1, ahalf = tid & 1;
    const char* aSrcH = (const char*)(g_hh + ((size_t)e * N_TOK + m0 + ar) * HID) + ahalf * 16;
    const char* aSrcL = (const char*)(g_hl + ((size_t)e * N_TOK + m0 + ar) * HID) + ahalf * 16;
    const uint32_t aDstH = sb + S_AH + ar * 48 + ahalf * 16;
    const uint32_t aDstL = sb + S_AL + ar * 48 + ahalf * 16;
    const int brow = (tid & 127) >> 3, bc = (tid & 7) * 16;
    const bool hi = tid < 128;
    const char* bSrc = (hi ? wh : wl) + (size_t)brow * DIM * 2 + n0 * 2 + bc;
    const uint32_t bDst = sb + (hi ? S_BH : S_BL) + brow * 144 + bc;

#define G_LOAD(k0, buf) do { \
        uint32_t _o = (uint32_t)(buf) * S_STG; \
        size_t _bk = (size_t)(k0) * DIM * 2; \
        CP_ASYNC16(aDstH + _o, aSrcH + (size_t)(k0) * 2); \
        CP_ASYNC16(aDstL + _o, aSrcL + (size_t)(k0) * 2); \
        CP_ASYNC16(bDst + _o, bSrc + _bk); \
        CP_COMMIT(); } while (0)

    const int wm = (wid & 3) * 32, wn = (wid >> 2) * 32;
    const int am = (lane & 7) + ((lane >> 3) & 1) * 8;
    const uint32_t ako = (lane >> 4) * 16;
    const uint32_t aBH = sb + S_AH + (wm + am) * 48 + ako;
    const uint32_t aBL = sb + S_AL + (wm + am) * 48 + ako;
    const int bk = lane & 15;
    const uint32_t bBH = sb + S_BH + bk * 144 + wn * 2;
    const uint32_t bBL = sb + S_BL + bk * 144 + wn * 2;

    float acc[2][4][4];
    #pragma unroll
    for (int i = 0; i < 2; i++)
        #pragma unroll
        for (int j = 0; j < 4; j++)
            #pragma unroll
            for (int q = 0; q < 4; q++) acc[i][j][q] = 0.f;

    G_LOAD(0, 0);
    G_LOAD(16, 1);
    CP_WAIT(1); __syncthreads();

    int cur = 0;
    for (int s = 0; s < 64; s++) {
        int ldb = cur + 2; if (ldb >= 3) ldb -= 3;
        if (s + 2 < 64) G_LOAD((s + 2) * 16, ldb);

        const uint32_t off = (uint32_t)cur * S_STG;
        uint32_t ah[2][4], al[2][4], bh[4][2], bl[4][2];
        #pragma unroll
        for (int i = 0; i < 2; i++) {
            ldsm_x4(ah[i], aBH + off + i * 768);
            ldsm_x4(al[i], aBL + off + i * 768);
        }
        #pragma unroll
        for (int j = 0; j < 4; j++) {
            ldsm_x2_t(bh[j], bBH + off + j * 16);
            ldsm_x2_t(bl[j], bBL + off + j * 16);
        }
        #pragma unroll
        for (int i = 0; i < 2; i++)
            #pragma unroll
            for (int j = 0; j < 4; j++) {
                mma_bf16(acc[i][j], ah[i], bh[j]);
                mma_bf16(acc[i][j], ah[i], bl[j]);
                mma_bf16(acc[i][j], al[i], bh[j]);
            }
        if (s + 2 < 64) CP_WAIT(1); else CP_WAIT(0);
        __syncthreads();
        cur++; if (cur == 3) cur = 0;
    }

    const int qr = lane >> 2, r4 = lane & 3;
    #pragma unroll
    for (int i = 0; i < 2; i++) {
        const int lr0 = wm + i * 16 + qr, lr1 = lr0 + 8;
        const bool ok0 = (m0 + lr0) < cnt, ok1 = (m0 + lr1) < cnt;
        float* d0 = g_rbuf + (size_t)s_dst[lr0] * DIM + n0;
        float* d1 = g_rbuf + (size_t)s_dst[lr1] * DIM + n0;
        #pragma unroll
        for (int j = 0; j < 4; j++) {
            const int col = wn + j * 8 + r4 * 2;
            if (ok0) *(float2*)(d0 + col) = make_float2(acc[i][j][0], acc[i][j][1]);
            if (ok1) *(float2*)(d1 + col) = make_float2(acc[i][j][2], acc[i][j][3]);
        }
    }
#undef G_LOAD
}

// ---------------- combine ---------------------------------------------------
__global__ void combine_kernel(float* __restrict__ out) {
    int i4 = blockIdx.x * 256 + threadIdx.x;
    int t  = i4 >> 8;
    float w0 = g_top_w[2 * t], w1 = g_top_w[2 * t + 1];
    float4 a = ((const float4*)g_rbuf)[i4];
    float4 b = ((const float4*)g_rbuf)[(size_t)(N_TOK * DIM / 4) + i4];
    float4 c = ((const float4*)g_rbuf)[(size_t)(2 * N_TOK * DIM / 4) + i4];
    float4 o;
    o.x = c.x + w0 * a.x + w1 * b.x;
    o.y = c.y + w0 * a.y + w1 * b.y;
    o.z = c.z + w0 * a.z + w1 * b.z;
    o.w = c.w + w0 * a.w + w1 * b.w;
    ((float4*)out)[i4] = o;
}

// ---------------- launch ----------------------------------------------------
extern "C" void kernel_launch(void* const* d_in, const int* in_sizes, int n_in,
                              void* d_out, int out_size)
{
    const float* x  = (const float*)d_in[0];
    const float* sg = (const float*)d_in[1];
    const float* su = (const float*)d_in[2];
    const float* sd = (const float*)d_in[3];
    const float* Wg = (const float*)d_in[4];
    const float* Wu = (const float*)d_in[5];
    const float* Wd = (const float*)d_in[6];
    const float* Wr = (const float*)d_in[7];
    const float* lt = (const float*)d_in[8];
    const int*   li = (const int*)d_in[9];
    float* out = (float*)d_out;
    (void)in_sizes; (void)n_in; (void)out_size;

    static int attr_done = 0;
    if (!attr_done) {
        cudaFuncSetAttribute(gemm1_kernel, cudaFuncAttributeMaxDynamicSharedMemorySize, 3 * S_STG);
        cudaFuncSetAttribute(gemm2_kernel, cudaFuncAttributeMaxDynamicSharedMemorySize, 3 * S_STG);
        attr_done = 1;
    }

    zero_kernel<<<1, 32>>>();
    convert_x_kernel<<<(N_TOK * DIM / 4) / 256, 256>>>(x);
    convert_w_kernel<<<dim3((DIM * HID / 4) / 256, 27), 256>>>(Wg, Wu, Wd, sg, su, sd);
    router_kernel<<<N_TOK / 32, 256>>>(x, Wr, lt, li);
    dispatch_kernel<<<N_TOK / 256, 256>>>();

    gemm1_kernel<<<dim3(32, 32, NSEG), 256, 3 * S_STG>>>();
    act_convert_kernel<<<NSEG * N_TOK / 8, 256>>>();
    gemm2_kernel<<<dim3(16, 32, NSEG), 256, 3 * S_STG>>>();
    combine_kernel<<<(N_TOK * (DIM / 4)) / 256, 256>>>(out);
}

// round 8
// speedup vs baseline: 3.9110x; 1.6644x over previous
#include <cuda_runtime.h>
#include <cuda_fp16.h>
#include <cstdint>

#define N_TOK 4096
#define DIM   1024
#define HID   1024
#define NE    8
#define NSEG  9

// ---------------- scratch ---------------------------------------------------
__device__ int   g_cnt[NSEG];
__device__ int   g_assign_token[NE * N_TOK];
__device__ int   g_assign_slot [NE * N_TOK];
__device__ int   g_top_e[N_TOK * 2];
__device__ float g_top_w[N_TOK * 2];
__device__ __half g_Xf[(size_t)N_TOK * DIM];
// 27 matrices [k][n]: Wg[0..7], Wu[8..15], Wd[16..23], sg=24, su=25, sd=26
__device__ __half g_Wh[(size_t)27 * DIM * HID];   // hi slice
__device__ __half g_Wl[(size_t)27 * DIM * HID];   // lo slice (residual)
__device__ __half g_Hf[(size_t)NSEG * N_TOK * HID];
__device__ float g_rbuf[(size_t)3 * N_TOK * DIM];

// ---------------- helpers ---------------------------------------------------
__device__ __forceinline__ uint32_t smem_u32(const void* p) {
    uint32_t a;
    asm("{ .reg .u64 t; cvta.to.shared.u64 t, %1; cvt.u32.u64 %0, t; }"
        : "=r"(a) : "l"(p));
    return a;
}
#define CP_ASYNC16(dst, src) \
    asm volatile("cp.async.cg.shared.global [%0], [%1], 16;" :: "r"(dst), "l"(src))
#define CP_COMMIT() asm volatile("cp.async.commit_group;" ::: "memory")
#define CP_WAIT(n)  asm volatile("cp.async.wait_group %0;" :: "n"(n) : "memory")

__device__ __forceinline__ void ldsm_x4(uint32_t* r, uint32_t addr) {
    asm volatile("ldmatrix.sync.aligned.m8n8.x4.shared.b16 {%0,%1,%2,%3}, [%4];"
        : "=r"(r[0]), "=r"(r[1]), "=r"(r[2]), "=r"(r[3]) : "r"(addr));
}
__device__ __forceinline__ void ldsm_x2_t(uint32_t* r, uint32_t addr) {
    asm volatile("ldmatrix.sync.aligned.m8n8.x2.trans.shared.b16 {%0,%1}, [%2];"
        : "=r"(r[0]), "=r"(r[1]) : "r"(addr));
}
__device__ __forceinline__ void mma_f16(float* d, const uint32_t* a, const uint32_t* b) {
    asm volatile(
        "mma.sync.aligned.m16n8k16.row.col.f32.f16.f16.f32 "
        "{%0,%1,%2,%3}, {%4,%5,%6,%7}, {%8,%9}, {%0,%1,%2,%3};"
        : "+f"(d[0]), "+f"(d[1]), "+f"(d[2]), "+f"(d[3])
        : "r"(a[0]), "r"(a[1]), "r"(a[2]), "r"(a[3]), "r"(b[0]), "r"(b[1]));
}
__device__ __forceinline__ float silu(float g) { return g / (1.f + __expf(-g)); }

__device__ __forceinline__ const float* pick_src(
    int m, const float* Wg, const float* Wu, const float* Wd,
    const float* sg, const float* su, const float* sd)
{
    if (m < 8)  return Wg + (size_t)m * DIM * HID;
    if (m < 16) return Wu + (size_t)(m - 8) * DIM * HID;
    if (m < 24) return Wd + (size_t)(m - 16) * DIM * HID;
    if (m == 24) return sg;
    if (m == 25) return su;
    return sd;
}

// ---------------- small kernels ---------------------------------------------
__global__ void zero_kernel() {
    int t = threadIdx.x;
    if (t < NE) g_cnt[t] = 0;
    if (t == NE) g_cnt[NE] = N_TOK;
}

__global__ void convert_x_kernel(const float* __restrict__ x) {
    size_t i4 = (size_t)blockIdx.x * 256 + threadIdx.x;
    float4 v = ((const float4*)x)[i4];
    __half2 a = __floats2half2_rn(v.x, v.y);
    __half2 b = __floats2half2_rn(v.z, v.w);
    ((uint2*)g_Xf)[i4] = make_uint2(*(uint32_t*)&a, *(uint32_t*)&b);
}

__global__ void convert_w_kernel(
    const float* __restrict__ Wg, const float* __restrict__ Wu,
    const float* __restrict__ Wd, const float* __restrict__ sg,
    const float* __restrict__ su, const float* __restrict__ sd)
{
    int m = blockIdx.y;
    const float* src = pick_src(m, Wg, Wu, Wd, sg, su, sd);
    size_t i4 = (size_t)blockIdx.x * 256 + threadIdx.x;
    float4 v = ((const float4*)src)[i4];
    __half h0 = __float2half_rn(v.x), h1 = __float2half_rn(v.y);
    __half h2 = __float2half_rn(v.z), h3 = __float2half_rn(v.w);
    __half l0 = __float2half_rn(v.x - __half2float(h0));
    __half l1 = __float2half_rn(v.y - __half2float(h1));
    __half l2 = __float2half_rn(v.z - __half2float(h2));
    __half l3 = __float2half_rn(v.w - __half2float(h3));
    __half2 ha; ha.x = h0; ha.y = h1;
    __half2 hb; hb.x = h2; hb.y = h3;
    __half2 la; la.x = l0; la.y = l1;
    __half2 lb; lb.x = l2; lb.y = l3;
    size_t o = (size_t)m * (DIM * HID / 4) + i4;
    ((uint2*)g_Wh)[o] = make_uint2(*(uint32_t*)&ha, *(uint32_t*)&hb);
    ((uint2*)g_Wl)[o] = make_uint2(*(uint32_t*)&la, *(uint32_t*)&lb);
}

__global__ __launch_bounds__(256, 4) void router_kernel(
    const float* __restrict__ X, const float* __restrict__ Wr,
    const float* __restrict__ loop_table, const int* __restrict__ loop_idx)
{
    __shared__ float4 sW[NE][256];
    __shared__ float s_bias[NE];
    const int tid = threadIdx.x, warp = tid >> 5, lane = tid & 31;

    for (int i = tid; i < NE * 256; i += 256) {
        int e = i >> 8, k4 = i & 255;
        sW[e][k4] = make_float4(Wr[(size_t)(k4 * 4 + 0) * NE + e],
                                Wr[(size_t)(k4 * 4 + 1) * NE + e],
                                Wr[(size_t)(k4 * 4 + 2) * NE + e],
                                Wr[(size_t)(k4 * 4 + 3) * NE + e]);
    }
    const float* le = loop_table + (size_t)loop_idx[0] * DIM;
    float b = 0.f;
    for (int d = lane; d < DIM; d += 32)
        b += le[d] * Wr[(size_t)(DIM + d) * NE + warp];
    #pragma unroll
    for (int o = 16; o; o >>= 1) b += __shfl_xor_sync(~0u, b, o);
    if (lane == 0) s_bias[warp] = b;
    __syncthreads();

    #pragma unroll 1
    for (int rep = 0; rep < 4; rep++) {
        const int t = blockIdx.x * 32 + warp * 4 + rep;
        const float4* xr = (const float4*)(X + (size_t)t * DIM);
        float acc[NE];
        #pragma unroll
        for (int e = 0; e < NE; e++) acc[e] = 0.f;
        #pragma unroll 1
        for (int i = 0; i < 8; i++) {
            float4 xv = xr[lane + 32 * i];
            const float4* swp = &sW[0][lane + 32 * i];
            #pragma unroll
            for (int e = 0; e < NE; e++) {
                float4 w = swp[e * 256];
                acc[e] += xv.x * w.x + xv.y * w.y + xv.z * w.z + xv.w * w.w;
            }
        }
        #pragma unroll
        for (int e = 0; e < NE; e++)
            #pragma unroll
            for (int o = 16; o; o >>= 1) acc[e] += __shfl_xor_sync(~0u, acc[e], o);

        if (lane == 0) {
            float p[NE];
            #pragma unroll
            for (int e = 0; e < NE; e++)
                p[e] = 1.f / (1.f + expf(-(acc[e] + s_bias[e])));
            int i0 = 0; float v0 = p[0];
            #pragma unroll
            for (int e = 1; e < NE; e++) if (p[e] > v0) { v0 = p[e]; i0 = e; }
            int i1 = -1; float v1 = -1e30f;
            #pragma unroll
            for (int e = 0; e < NE; e++) {
                if (e == i0) continue;
                if (p[e] > v1) { v1 = p[e]; i1 = e; }
            }
            g_top_e[t * 2 + 0] = i0;  g_top_e[t * 2 + 1] = i1;
            g_top_w[t * 2 + 0] = v0;  g_top_w[t * 2 + 1] = v1;
        }
    }
}

__global__ void dispatch_kernel() {
    int t = blockIdx.x * blockDim.x + threadIdx.x;
    if (t >= N_TOK) return;
    #pragma unroll
    for (int k = 0; k < 2; k++) {
        int e = g_top_e[t * 2 + k];
        int pos = atomicAdd(&g_cnt[e], 1);
        g_assign_token[e * N_TOK + pos] = t;
        g_assign_slot [e * N_TOK + pos] = k;
    }
}

// ---------------- GEMM1: X @ {Wg,Wu}[e], fused SiLU -> fp16 h ---------------
// Block 128m x 64n (both gate and up), BK=16, 3-stage cp.async.
// warps 4m x 2n: warp = 32m x 32n per matrix.
#define S1_A  0u
#define S1_GH 6144u
#define S1_GL 8448u
#define S1_UH 10752u
#define S1_UL 13056u
#define S1_STG 15360u

__global__ __launch_bounds__(256) void gemm1_kernel() {
    extern __shared__ char sm[];
    __shared__ int s_token[128];

    const int e   = blockIdx.z;
    const int cnt = g_cnt[e];
    const int m0  = blockIdx.y * 128;
    if (m0 >= cnt) return;
    const int n0  = blockIdx.x * 64;
    const int tid = threadIdx.x, wid = tid >> 5, lane = tid & 31;

    const int ig = (e < NE) ? e : 24;
    const int iu = (e < NE) ? 8 + e : 25;

    if (tid < 128) {
        int r = m0 + tid;
        s_token[tid] = (e < NE) ? ((r < cnt) ? g_assign_token[e * N_TOK + r] : 0) : r;
    }
    __syncthreads();
    const uint32_t sb = smem_u32(sm);

    const char* wgh = (const char*)(g_Wh + (size_t)ig * DIM * HID);
    const char* wgl = (const char*)(g_Wl + (size_t)ig * DIM * HID);
    const char* wuh = (const char*)(g_Wh + (size_t)iu * DIM * HID);
    const char* wul = (const char*)(g_Wl + (size_t)iu * DIM * HID);

    const int ar = tid >> 1, ahalf = tid & 1;
    const char* aSrc = (const char*)(g_Xf + (size_t)s_token[ar] * DIM) + ahalf * 16;
    const uint32_t aDst = sb + S1_A + ar * 48 + ahalf * 16;
    const int brow = (tid & 127) >> 3, bc = (tid & 7) * 16;
    const bool hi = tid < 128;
    const char* bSrcG = (hi ? wgh : wgl) + (size_t)brow * HID * 2 + n0 * 2 + bc;
    const char* bSrcU = (hi ? wuh : wul) + (size_t)brow * HID * 2 + n0 * 2 + bc;
    const uint32_t bDstG = sb + (hi ? S1_GH : S1_GL) + brow * 144 + bc;
    const uint32_t bDstU = sb + (hi ? S1_UH : S1_UL) + brow * 144 + bc;

#define G_LOAD(k0, buf) do { \
        uint32_t _o = (uint32_t)(buf) * S1_STG; \
        size_t _bk = (size_t)(k0) * HID * 2; \
        CP_ASYNC16(aDst + _o, aSrc + (size_t)(k0) * 2); \
        CP_ASYNC16(bDstG + _o, bSrcG + _bk); \
        CP_ASYNC16(bDstU + _o, bSrcU + _bk); \
        CP_COMMIT(); } while (0)

    const int wm = (wid & 3) * 32, wn = (wid >> 2) * 32;
    const int am = (lane & 7) + ((lane >> 3) & 1) * 8;
    const uint32_t ako = (lane >> 4) * 16;
    const uint32_t aB = sb + S1_A + (wm + am) * 48 + ako;
    const int bk = lane & 15;
    const uint32_t bGH = sb + S1_GH + bk * 144 + wn * 2;
    const uint32_t bGL = sb + S1_GL + bk * 144 + wn * 2;
    const uint32_t bUH = sb + S1_UH + bk * 144 + wn * 2;
    const uint32_t bUL = sb + S1_UL + bk * 144 + wn * 2;

    float accG[2][4][4], accU[2][4][4];
    #pragma unroll
    for (int i = 0; i < 2; i++)
        #pragma unroll
        for (int j = 0; j < 4; j++)
            #pragma unroll
            for (int q = 0; q < 4; q++) { accG[i][j][q] = 0.f; accU[i][j][q] = 0.f; }

    G_LOAD(0, 0);
    G_LOAD(16, 1);
    CP_WAIT(1); __syncthreads();

    int cur = 0;
    for (int s = 0; s < 64; s++) {
        int ldb = cur + 2; if (ldb >= 3) ldb -= 3;
        if (s + 2 < 64) G_LOAD((s + 2) * 16, ldb);

        const uint32_t off = (uint32_t)cur * S1_STG;
        uint32_t a[2][4], bgh[4][2], bgl[4][2], buh[4][2], bul[4][2];
        #pragma unroll
        for (int i = 0; i < 2; i++) ldsm_x4(a[i], aB + off + i * 768);
        #pragma unroll
        for (int j = 0; j < 4; j++) {
            ldsm_x2_t(bgh[j], bGH + off + j * 16);
            ldsm_x2_t(bgl[j], bGL + off + j * 16);
            ldsm_x2_t(buh[j], bUH + off + j * 16);
            ldsm_x2_t(bul[j], bUL + off + j * 16);
        }
        #pragma unroll
        for (int i = 0; i < 2; i++)
            #pragma unroll
            for (int j = 0; j < 4; j++) {
                mma_f16(accG[i][j], a[i], bgh[j]);
                mma_f16(accG[i][j], a[i], bgl[j]);
                mma_f16(accU[i][j], a[i], buh[j]);
                mma_f16(accU[i][j], a[i], bul[j]);
            }
        if (s + 2 < 64) CP_WAIT(1); else CP_WAIT(0);
        __syncthreads();
        cur++; if (cur == 3) cur = 0;
    }

    const int qr = lane >> 2, r4 = lane & 3;
    #pragma unroll
    for (int i = 0; i < 2; i++) {
        const int lr0 = wm + i * 16 + qr, lr1 = lr0 + 8;
        const bool ok0 = (m0 + lr0) < cnt, ok1 = (m0 + lr1) < cnt;
        __half* d0 = g_Hf + ((size_t)e * N_TOK + m0 + lr0) * HID + n0;
        __half* d1 = g_Hf + ((size_t)e * N_TOK + m0 + lr1) * HID + n0;
        #pragma unroll
        for (int j = 0; j < 4; j++) {
            const int col = wn + j * 8 + r4 * 2;
            float h00 = silu(accG[i][j][0]) * accU[i][j][0];
            float h01 = silu(accG[i][j][1]) * accU[i][j][1];
            float h10 = silu(accG[i][j][2]) * accU[i][j][2];
            float h11 = silu(accG[i][j][3]) * accU[i][j][3];
            if (ok0) *(__half2*)(d0 + col) = __floats2half2_rn(h00, h01);
            if (ok1) *(__half2*)(d1 + col) = __floats2half2_rn(h10, h11);
        }
    }
#undef G_LOAD
}

// ---------------- GEMM2: h @ Wd[e] -> scattered fp32 rbuf -------------------
// Block 128m x 64n, warps 4m x 2n.
#define S2_A  0u
#define S2_BH 6144u
#define S2_BL 8448u
#define S2_STG 10752u

__global__ __launch_bounds__(256, 2) void gemm2_kernel() {
    extern __shared__ char sm[];
    __shared__ int s_dst[128];

    const int e   = blockIdx.z;
    const int cnt = g_cnt[e];
    const int m0  = blockIdx.y * 128;
    if (m0 >= cnt) return;
    const int n0  = blockIdx.x * 64;
    const int tid = threadIdx.x, wid = tid >> 5, lane = tid & 31;

    const int id = (e < NE) ? 16 + e : 26;

    if (tid < 128) {
        int r = m0 + tid, dst = 0;
        if (r < cnt) {
            if (e < NE)
                dst = g_assign_slot[e * N_TOK + r] * N_TOK + g_assign_token[e * N_TOK + r];
            else
                dst = 2 * N_TOK + r;
        }
        s_dst[tid] = dst;
    }
    __syncthreads();
    const uint32_t sb = smem_u32(sm);

    const char* wh = (const char*)(g_Wh + (size_t)id * DIM * HID);
    const char* wl = (const char*)(g_Wl + (size_t)id * DIM * HID);

    const int ar = tid >> 1, ahalf = tid & 1;
    const char* aSrc = (const char*)(g_Hf + ((size_t)e * N_TOK + m0 + ar) * HID) + ahalf * 16;
    const uint32_t aDst = sb + S2_A + ar * 48 + ahalf * 16;
    const int brow = (tid & 127) >> 3, bc = (tid & 7) * 16;
    const bool hi = tid < 128;
    const char* bSrc = (hi ? wh : wl) + (size_t)brow * DIM * 2 + n0 * 2 + bc;
    const uint32_t bDst = sb + (hi ? S2_BH : S2_BL) + brow * 144 + bc;

#define G_LOAD(k0, buf) do { \
        uint32_t _o = (uint32_t)(buf) * S2_STG; \
        size_t _bk = (size_t)(k0) * DIM * 2; \
        CP_ASYNC16(aDst + _o, aSrc + (size_t)(k0) * 2); \
        CP_ASYNC16(bDst + _o, bSrc + _bk); \
        CP_COMMIT(); } while (0)

    const int wm = (wid & 3) * 32, wn = (wid >> 2) * 32;
    const int am = (lane & 7) + ((lane >> 3) & 1) * 8;
    const uint32_t ako = (lane >> 4) * 16;
    const uint32_t aB = sb + S2_A + (wm + am) * 48 + ako;
    const int bk = lane & 15;
    const uint32_t bBH = sb + S2_BH + bk * 144 + wn * 2;
    const uint32_t bBL = sb + S2_BL + bk * 144 + wn * 2;

    float acc[2][4][4];
    #pragma unroll
    for (int i = 0; i < 2; i++)
        #pragma unroll
        for (int j = 0; j < 4; j++)
            #pragma unroll
            for (int q = 0; q < 4; q++) acc[i][j][q] = 0.f;

    G_LOAD(0, 0);
    G_LOAD(16, 1);
    CP_WAIT(1); __syncthreads();

    int cur = 0;
    for (int s = 0; s < 64; s++) {
        int ldb = cur + 2; if (ldb >= 3) ldb -= 3;
        if (s + 2 < 64) G_LOAD((s + 2) * 16, ldb);

        const uint32_t off = (uint32_t)cur * S2_STG;
        uint32_t a[2][4], bh[4][2], bl[4][2];
        #pragma unroll
        for (int i = 0; i < 2; i++) ldsm_x4(a[i], aB + off + i * 768);
        #pragma unroll
        for (int j = 0; j < 4; j++) {
            ldsm_x2_t(bh[j], bBH + off + j * 16);
            ldsm_x2_t(bl[j], bBL + off + j * 16);
        }
        #pragma unroll
        for (int i = 0; i < 2; i++)
            #pragma unroll
            for (int j = 0; j < 4; j++) {
                mma_f16(acc[i][j], a[i], bh[j]);
                mma_f16(acc[i][j], a[i], bl[j]);
            }
        if (s + 2 < 64) CP_WAIT(1); else CP_WAIT(0);
        __syncthreads();
        cur++; if (cur == 3) cur = 0;
    }

    const int qr = lane >> 2, r4 = lane & 3;
    #pragma unroll
    for (int i = 0; i < 2; i++) {
        const int lr0 = wm + i * 16 + qr, lr1 = lr0 + 8;
        const bool ok0 = (m0 + lr0) < cnt, ok1 = (m0 + lr1) < cnt;
        float* d0 = g_rbuf + (size_t)s_dst[lr0] * DIM + n0;
        float* d1 = g_rbuf + (size_t)s_dst[lr1] * DIM + n0;
        #pragma unroll
        for (int j = 0; j < 4; j++) {
            const int col = wn + j * 8 + r4 * 2;
            if (ok0) *(float2*)(d0 + col) = make_float2(acc[i][j][0], acc[i][j][1]);
            if (ok1) *(float2*)(d1 + col) = make_float2(acc[i][j][2], acc[i][j][3]);
        }
    }
#undef G_LOAD
}

// ---------------- combine ---------------------------------------------------
__global__ void combine_kernel(float* __restrict__ out) {
    int i4 = blockIdx.x * 256 + threadIdx.x;
    int t  = i4 >> 8;
    float w0 = g_top_w[2 * t], w1 = g_top_w[2 * t + 1];
    float4 a = ((const float4*)g_rbuf)[i4];
    float4 b = ((const float4*)g_rbuf)[(size_t)(N_TOK * DIM / 4) + i4];
    float4 c = ((const float4*)g_rbuf)[(size_t)(2 * N_TOK * DIM / 4) + i4];
    float4 o;
    o.x = c.x + w0 * a.x + w1 * b.x;
    o.y = c.y + w0 * a.y + w1 * b.y;
    o.z = c.z + w0 * a.z + w1 * b.z;
    o.w = c.w + w0 * a.w + w1 * b.w;
    ((float4*)out)[i4] = o;
}

// ---------------- launch ----------------------------------------------------
extern "C" void kernel_launch(void* const* d_in, const int* in_sizes, int n_in,
                              void* d_out, int out_size)
{
    const float* x  = (const float*)d_in[0];
    const float* sg = (const float*)d_in[1];
    const float* su = (const float*)d_in[2];
    const float* sd = (const float*)d_in[3];
    const float* Wg = (const float*)d_in[4];
    const float* Wu = (const float*)d_in[5];
    const float* Wd = (const float*)d_in[6];
    const float* Wr = (const float*)d_in[7];
    const float* lt = (const float*)d_in[8];
    const int*   li = (const int*)d_in[9];
    float* out = (float*)d_out;
    (void)in_sizes; (void)n_in; (void)out_size;

    static int attr_done = 0;
    if (!attr_done) {
        cudaFuncSetAttribute(gemm1_kernel, cudaFuncAttributeMaxDynamicSharedMemorySize, 3 * S1_STG);
        cudaFuncSetAttribute(gemm2_kernel, cudaFuncAttributeMaxDynamicSharedMemorySize, 3 * S2_STG);
        attr_done = 1;
    }

    zero_kernel<<<1, 32>>>();
    convert_x_kernel<<<(N_TOK * DIM / 4) / 256, 256>>>(x);
    convert_w_kernel<<<dim3((DIM * HID / 4) / 256, 27), 256>>>(Wg, Wu, Wd, sg, su, sd);
    router_kernel<<<N_TOK / 32, 256>>>(x, Wr, lt, li);
    dispatch_kernel<<<N_TOK / 256, 256>>>();

    gemm1_kernel<<<dim3(16, 32, NSEG), 256, 3 * S1_STG>>>();
    gemm2_kernel<<<dim3(16, 32, NSEG), 256, 3 * S2_STG>>>();
    combine_kernel<<<(N_TOK * (DIM / 4)) / 256, 256>>>(out);
}

// round 9
// speedup vs baseline: 5.4551x; 1.3948x over previous
#include <cuda_runtime.h>
#include <cuda_fp16.h>
#include <cstdint>

#define N_TOK 4096
#define DIM   1024
#define HID   1024
#define NE    8
#define NSEG  9

// ---------------- scratch ---------------------------------------------------
__device__ int   g_cnt[NSEG];
__device__ int   g_assign_token[NE * N_TOK];
__device__ int   g_assign_slot [NE * N_TOK];
__device__ int   g_top_e[N_TOK * 2];
__device__ float g_top_w[N_TOK * 2];
__device__ __half g_Xf[(size_t)N_TOK * DIM];
// 27 matrices [k][n]: Wg[0..7], Wu[8..15], Wd[16..23], sg=24, su=25, sd=26
__device__ __half g_Wf[(size_t)27 * DIM * HID];
__device__ __half g_Hf[(size_t)NSEG * N_TOK * HID];
__device__ float g_rbuf[(size_t)3 * N_TOK * DIM];

// ---------------- helpers ---------------------------------------------------
__device__ __forceinline__ uint32_t smem_u32(const void* p) {
    uint32_t a;
    asm("{ .reg .u64 t; cvta.to.shared.u64 t, %1; cvt.u32.u64 %0, t; }"
        : "=r"(a) : "l"(p));
    return a;
}
#define CP_ASYNC16(dst, src) \
    asm volatile("cp.async.cg.shared.global [%0], [%1], 16;" :: "r"(dst), "l"(src))
#define CP_COMMIT() asm volatile("cp.async.commit_group;" ::: "memory")
#define CP_WAIT(n)  asm volatile("cp.async.wait_group %0;" :: "n"(n) : "memory")

__device__ __forceinline__ void ldsm_x4(uint32_t* r, uint32_t addr) {
    asm volatile("ldmatrix.sync.aligned.m8n8.x4.shared.b16 {%0,%1,%2,%3}, [%4];"
        : "=r"(r[0]), "=r"(r[1]), "=r"(r[2]), "=r"(r[3]) : "r"(addr));
}
__device__ __forceinline__ void ldsm_x2_t(uint32_t* r, uint32_t addr) {
    asm volatile("ldmatrix.sync.aligned.m8n8.x2.trans.shared.b16 {%0,%1}, [%2];"
        : "=r"(r[0]), "=r"(r[1]) : "r"(addr));
}
__device__ __forceinline__ void mma_f16(float* d, const uint32_t* a, const uint32_t* b) {
    asm volatile(
        "mma.sync.aligned.m16n8k16.row.col.f32.f16.f16.f32 "
        "{%0,%1,%2,%3}, {%4,%5,%6,%7}, {%8,%9}, {%0,%1,%2,%3};"
        : "+f"(d[0]), "+f"(d[1]), "+f"(d[2]), "+f"(d[3])
        : "r"(a[0]), "r"(a[1]), "r"(a[2]), "r"(a[3]), "r"(b[0]), "r"(b[1]));
}
__device__ __forceinline__ float silu(float g) { return g / (1.f + __expf(-g)); }

__device__ __forceinline__ const float* pick_src(
    int m, const float* Wg, const float* Wu, const float* Wd,
    const float* sg, const float* su, const float* sd)
{
    if (m < 8)  return Wg + (size_t)m * DIM * HID;
    if (m < 16) return Wu + (size_t)(m - 8) * DIM * HID;
    if (m < 24) return Wd + (size_t)(m - 16) * DIM * HID;
    if (m == 24) return sg;
    if (m == 25) return su;
    return sd;
}

// ---------------- small kernels ---------------------------------------------
__global__ void zero_kernel() {
    int t = threadIdx.x;
    if (t < NE) g_cnt[t] = 0;
    if (t == NE) g_cnt[NE] = N_TOK;
}

__global__ void convert_x_kernel(const float* __restrict__ x) {
    size_t i4 = (size_t)blockIdx.x * 256 + threadIdx.x;
    float4 v = ((const float4*)x)[i4];
    __half2 a = __floats2half2_rn(v.x, v.y);
    __half2 b = __floats2half2_rn(v.z, v.w);
    ((uint2*)g_Xf)[i4] = make_uint2(*(uint32_t*)&a, *(uint32_t*)&b);
}

__global__ void convert_w_kernel(
    const float* __restrict__ Wg, const float* __restrict__ Wu,
    const float* __restrict__ Wd, const float* __restrict__ sg,
    const float* __restrict__ su, const float* __restrict__ sd)
{
    int m = blockIdx.y;
    const float* src = pick_src(m, Wg, Wu, Wd, sg, su, sd);
    size_t i4 = (size_t)blockIdx.x * 256 + threadIdx.x;
    float4 v = ((const float4*)src)[i4];
    __half2 a = __floats2half2_rn(v.x, v.y);
    __half2 b = __floats2half2_rn(v.z, v.w);
    size_t o = (size_t)m * (DIM * HID / 4) + i4;
    ((uint2*)g_Wf)[o] = make_uint2(*(uint32_t*)&a, *(uint32_t*)&b);
}

__global__ __launch_bounds__(256, 4) void router_kernel(
    const float* __restrict__ X, const float* __restrict__ Wr,
    const float* __restrict__ loop_table, const int* __restrict__ loop_idx)
{
    __shared__ float4 sW[NE][256];
    __shared__ float s_bias[NE];
    const int tid = threadIdx.x, warp = tid >> 5, lane = tid & 31;

    for (int i = tid; i < NE * 256; i += 256) {
        int e = i >> 8, k4 = i & 255;
        sW[e][k4] = make_float4(Wr[(size_t)(k4 * 4 + 0) * NE + e],
                                Wr[(size_t)(k4 * 4 + 1) * NE + e],
                                Wr[(size_t)(k4 * 4 + 2) * NE + e],
                                Wr[(size_t)(k4 * 4 + 3) * NE + e]);
    }
    const float* le = loop_table + (size_t)loop_idx[0] * DIM;
    float b = 0.f;
    for (int d = lane; d < DIM; d += 32)
        b += le[d] * Wr[(size_t)(DIM + d) * NE + warp];
    #pragma unroll
    for (int o = 16; o; o >>= 1) b += __shfl_xor_sync(~0u, b, o);
    if (lane == 0) s_bias[warp] = b;
    __syncthreads();

    #pragma unroll 1
    for (int rep = 0; rep < 4; rep++) {
        const int t = blockIdx.x * 32 + warp * 4 + rep;
        const float4* xr = (const float4*)(X + (size_t)t * DIM);
        float acc[NE];
        #pragma unroll
        for (int e = 0; e < NE; e++) acc[e] = 0.f;
        #pragma unroll 1
        for (int i = 0; i < 8; i++) {
            float4 xv = xr[lane + 32 * i];
            const float4* swp = &sW[0][lane + 32 * i];
            #pragma unroll
            for (int e = 0; e < NE; e++) {
                float4 w = swp[e * 256];
                acc[e] += xv.x * w.x + xv.y * w.y + xv.z * w.z + xv.w * w.w;
            }
        }
        #pragma unroll
        for (int e = 0; e < NE; e++)
            #pragma unroll
            for (int o = 16; o; o >>= 1) acc[e] += __shfl_xor_sync(~0u, acc[e], o);

        if (lane == 0) {
            float p[NE];
            #pragma unroll
            for (int e = 0; e < NE; e++)
                p[e] = 1.f / (1.f + expf(-(acc[e] + s_bias[e])));
            int i0 = 0; float v0 = p[0];
            #pragma unroll
            for (int e = 1; e < NE; e++) if (p[e] > v0) { v0 = p[e]; i0 = e; }
            int i1 = -1; float v1 = -1e30f;
            #pragma unroll
            for (int e = 0; e < NE; e++) {
                if (e == i0) continue;
                if (p[e] > v1) { v1 = p[e]; i1 = e; }
            }
            g_top_e[t * 2 + 0] = i0;  g_top_e[t * 2 + 1] = i1;
            g_top_w[t * 2 + 0] = v0;  g_top_w[t * 2 + 1] = v1;
        }
    }
}

__global__ void dispatch_kernel() {
    int t = blockIdx.x * blockDim.x + threadIdx.x;
    if (t >= N_TOK) return;
    #pragma unroll
    for (int k = 0; k < 2; k++) {
        int e = g_top_e[t * 2 + k];
        int pos = atomicAdd(&g_cnt[e], 1);
        g_assign_token[e * N_TOK + pos] = t;
        g_assign_slot [e * N_TOK + pos] = k;
    }
}

// ---------------- GEMM1: X @ {Wg,Wu}[e], fused SiLU -> fp16 h ---------------
// Block 128m x 64n (gate AND up), BK=16, 3-stage cp.async.
// warps 4m x 2n: warp = 32m x 32n per matrix.
#define S1_A  0u
#define S1_G  6144u
#define S1_U  8448u
#define S1_STG 10752u

__global__ __launch_bounds__(256) void gemm1_kernel() {
    extern __shared__ char sm[];
    __shared__ int s_token[128];

    const int e   = blockIdx.z;
    const int cnt = g_cnt[e];
    const int m0  = blockIdx.y * 128;
    if (m0 >= cnt) return;
    const int n0  = blockIdx.x * 64;
    const int tid = threadIdx.x, wid = tid >> 5, lane = tid & 31;

    const int ig = (e < NE) ? e : 24;
    const int iu = (e < NE) ? 8 + e : 25;

    if (tid < 128) {
        int r = m0 + tid;
        s_token[tid] = (e < NE) ? ((r < cnt) ? g_assign_token[e * N_TOK + r] : 0) : r;
    }
    __syncthreads();
    const uint32_t sb = smem_u32(sm);

    const char* wg = (const char*)(g_Wf + (size_t)ig * DIM * HID);
    const char* wu = (const char*)(g_Wf + (size_t)iu * DIM * HID);

    const int ar = tid >> 1, ahalf = tid & 1;
    const char* aSrc = (const char*)(g_Xf + (size_t)s_token[ar] * DIM) + ahalf * 16;
    const uint32_t aDst = sb + S1_A + ar * 48 + ahalf * 16;
    // B loaders: 256 threads cover 16 k-rows x 64 n (128B) for G and U
    const int brow = (tid & 127) >> 3, bc = (tid & 7) * 16;
    const bool isG = tid < 128;
    const char* bSrc = (isG ? wg : wu) + (size_t)brow * HID * 2 + n0 * 2 + bc;
    const uint32_t bDst = sb + (isG ? S1_G : S1_U) + brow * 144 + bc;

#define G_LOAD(k0, buf) do { \
        uint32_t _o = (uint32_t)(buf) * S1_STG; \
        size_t _bk = (size_t)(k0) * HID * 2; \
        CP_ASYNC16(aDst + _o, aSrc + (size_t)(k0) * 2); \
        CP_ASYNC16(bDst + _o, bSrc + _bk); \
        CP_COMMIT(); } while (0)

    const int wm = (wid & 3) * 32, wn = (wid >> 2) * 32;
    const int am = (lane & 7) + ((lane >> 3) & 1) * 8;
    const uint32_t ako = (lane >> 4) * 16;
    const uint32_t aB = sb + S1_A + (wm + am) * 48 + ako;
    const int bk = lane & 15;
    const uint32_t bG = sb + S1_G + bk * 144 + wn * 2;
    const uint32_t bU = sb + S1_U + bk * 144 + wn * 2;

    float accG[2][4][4], accU[2][4][4];
    #pragma unroll
    for (int i = 0; i < 2; i++)
        #pragma unroll
        for (int j = 0; j < 4; j++)
            #pragma unroll
            for (int q = 0; q < 4; q++) { accG[i][j][q] = 0.f; accU[i][j][q] = 0.f; }

    G_LOAD(0, 0);
    G_LOAD(16, 1);
    CP_WAIT(1); __syncthreads();

    int cur = 0;
    for (int s = 0; s < 64; s++) {
        int ldb = cur + 2; if (ldb >= 3) ldb -= 3;
        if (s + 2 < 64) G_LOAD((s + 2) * 16, ldb);

        const uint32_t off = (uint32_t)cur * S1_STG;
        uint32_t a[2][4], bg[4][2], bu[4][2];
        #pragma unroll
        for (int i = 0; i < 2; i++) ldsm_x4(a[i], aB + off + i * 768);
        #pragma unroll
        for (int j = 0; j < 4; j++) {
            ldsm_x2_t(bg[j], bG + off + j * 16);
            ldsm_x2_t(bu[j], bU + off + j * 16);
        }
        #pragma unroll
        for (int i = 0; i < 2; i++)
            #pragma unroll
            for (int j = 0; j < 4; j++) {
                mma_f16(accG[i][j], a[i], bg[j]);
                mma_f16(accU[i][j], a[i], bu[j]);
            }
        if (s + 2 < 64) CP_WAIT(1); else CP_WAIT(0);
        __syncthreads();
        cur++; if (cur == 3) cur = 0;
    }

    const int qr = lane >> 2, r4 = lane & 3;
    #pragma unroll
    for (int i = 0; i < 2; i++) {
        const int lr0 = wm + i * 16 + qr, lr1 = lr0 + 8;
        const bool ok0 = (m0 + lr0) < cnt, ok1 = (m0 + lr1) < cnt;
        __half* d0 = g_Hf + ((size_t)e * N_TOK + m0 + lr0) * HID + n0;
        __half* d1 = g_Hf + ((size_t)e * N_TOK + m0 + lr1) * HID + n0;
        #pragma unroll
        for (int j = 0; j < 4; j++) {
            const int col = wn + j * 8 + r4 * 2;
            float h00 = silu(accG[i][j][0]) * accU[i][j][0];
            float h01 = silu(accG[i][j][1]) * accU[i][j][1];
            float h10 = silu(accG[i][j][2]) * accU[i][j][2];
            float h11 = silu(accG[i][j][3]) * accU[i][j][3];
            if (ok0) *(__half2*)(d0 + col) = __floats2half2_rn(h00, h01);
            if (ok1) *(__half2*)(d1 + col) = __floats2half2_rn(h10, h11);
        }
    }
#undef G_LOAD
}

// ---------------- GEMM2: h @ Wd[e] -> scattered fp32 rbuf -------------------
// Block 128m x 64n, warps 4m x 2n.
#define S2_A  0u
#define S2_B  6144u
#define S2_STG 8448u

__global__ __launch_bounds__(256) void gemm2_kernel() {
    extern __shared__ char sm[];
    __shared__ int s_dst[128];

    const int e   = blockIdx.z;
    const int cnt = g_cnt[e];
    const int m0  = blockIdx.y * 128;
    if (m0 >= cnt) return;
    const int n0  = blockIdx.x * 64;
    const int tid = threadIdx.x, wid = tid >> 5, lane = tid & 31;

    const int id = (e < NE) ? 16 + e : 26;

    if (tid < 128) {
        int r = m0 + tid, dst = 0;
        if (r < cnt) {
            if (e < NE)
                dst = g_assign_slot[e * N_TOK + r] * N_TOK + g_assign_token[e * N_TOK + r];
            else
                dst = 2 * N_TOK + r;
        }
        s_dst[tid] = dst;
    }
    __syncthreads();
    const uint32_t sb = smem_u32(sm);

    const char* wd = (const char*)(g_Wf + (size_t)id * DIM * HID);

    const int ar = tid >> 1, ahalf = tid & 1;
    const char* aSrc = (const char*)(g_Hf + ((size_t)e * N_TOK + m0 + ar) * HID) + ahalf * 16;
    const uint32_t aDst = sb + S2_A + ar * 48 + ahalf * 16;
    // B loaders: first 128 threads cover 16 k-rows x 64 n
    const int brow = (tid & 127) >> 3, bc = (tid & 7) * 16;
    const char* bSrc = wd + (size_t)brow * DIM * 2 + n0 * 2 + bc;
    const uint32_t bDst = sb + S2_B + brow * 144 + bc;
    const bool bAct = tid < 128;

#define G_LOAD(k0, buf) do { \
        uint32_t _o = (uint32_t)(buf) * S2_STG; \
        size_t _bk = (size_t)(k0) * DIM * 2; \
        CP_ASYNC16(aDst + _o, aSrc + (size_t)(k0) * 2); \
        if (bAct) CP_ASYNC16(bDst + _o, bSrc + _bk); \
        CP_COMMIT(); } while (0)

    const int wm = (wid & 3) * 32, wn = (wid >> 2) * 32;
    const int am = (lane & 7) + ((lane >> 3) & 1) * 8;
    const uint32_t ako = (lane >> 4) * 16;
    const uint32_t aB = sb + S2_A + (wm + am) * 48 + ako;
    const int bk = lane & 15;
    const uint32_t bB = sb + S2_B + bk * 144 + wn * 2;

    float acc[2][4][4];
    #pragma unroll
    for (int i = 0; i < 2; i++)
        #pragma unroll
        for (int j = 0; j < 4; j++)
            #pragma unroll
            for (int q = 0; q < 4; q++) acc[i][j][q] = 0.f;

    G_LOAD(0, 0);
    G_LOAD(16, 1);
    CP_WAIT(1); __syncthreads();

    int cur = 0;
    for (int s = 0; s < 64; s++) {
        int ldb = cur + 2; if (ldb >= 3) ldb -= 3;
        if (s + 2 < 64) G_LOAD((s + 2) * 16, ldb);

        const uint32_t off = (uint32_t)cur * S2_STG;
        uint32_t a[2][4], b[4][2];
        #pragma unroll
        for (int i = 0; i < 2; i++) ldsm_x4(a[i], aB + off + i * 768);
        #pragma unroll
        for (int j = 0; j < 4; j++) ldsm_x2_t(b[j], bB + off + j * 16);
        #pragma unroll
        for (int i = 0; i < 2; i++)
            #pragma unroll
            for (int j = 0; j < 4; j++)
                mma_f16(acc[i][j], a[i], b[j]);
        if (s + 2 < 64) CP_WAIT(1); else CP_WAIT(0);
        __syncthreads();
        cur++; if (cur == 3) cur = 0;
    }

    const int qr = lane >> 2, r4 = lane & 3;
    #pragma unroll
    for (int i = 0; i < 2; i++) {
        const int lr0 = wm + i * 16 + qr, lr1 = lr0 + 8;
        const bool ok0 = (m0 + lr0) < cnt, ok1 = (m0 + lr1) < cnt;
        float* d0 = g_rbuf + (size_t)s_dst[lr0] * DIM + n0;
        float* d1 = g_rbuf + (size_t)s_dst[lr1] * DIM + n0;
        #pragma unroll
        for (int j = 0; j < 4; j++) {
            const int col = wn + j * 8 + r4 * 2;
            if (ok0) *(float2*)(d0 + col) = make_float2(acc[i][j][0], acc[i][j][1]);
            if (ok1) *(float2*)(d1 + col) = make_float2(acc[i][j][2], acc[i][j][3]);
        }
    }
#undef G_LOAD
}

// ---------------- combine ---------------------------------------------------
__global__ void combine_kernel(float* __restrict__ out) {
    int i4 = blockIdx.x * 256 + threadIdx.x;
    int t  = i4 >> 8;
    float w0 = g_top_w[2 * t], w1 = g_top_w[2 * t + 1];
    float4 a = ((const float4*)g_rbuf)[i4];
    float4 b = ((const float4*)g_rbuf)[(size_t)(N_TOK * DIM / 4) + i4];
    float4 c = ((const float4*)g_rbuf)[(size_t)(2 * N_TOK * DIM / 4) + i4];
    float4 o;
    o.x = c.x + w0 * a.x + w1 * b.x;
    o.y = c.y + w0 * a.y + w1 * b.y;
    o.z = c.z + w0 * a.z + w1 * b.z;
    o.w = c.w + w0 * a.w + w1 * b.w;
    ((float4*)out)[i4] = o;
}

// ---------------- launch ----------------------------------------------------
extern "C" void kernel_launch(void* const* d_in, const int* in_sizes, int n_in,
                              void* d_out, int out_size)
{
    const float* x  = (const float*)d_in[0];
    const float* sg = (const float*)d_in[1];
    const float* su = (const float*)d_in[2];
    const float* sd = (const float*)d_in[3];
    const float* Wg = (const float*)d_in[4];
    const float* Wu = (const float*)d_in[5];
    const float* Wd = (const float*)d_in[6];
    const float* Wr = (const float*)d_in[7];
    const float* lt = (const float*)d_in[8];
    const int*   li = (const int*)d_in[9];
    float* out = (float*)d_out;
    (void)in_sizes; (void)n_in; (void)out_size;

    static int attr_done = 0;
    if (!attr_done) {
        cudaFuncSetAttribute(gemm1_kernel, cudaFuncAttributeMaxDynamicSharedMemorySize, 3 * S1_STG);
        cudaFuncSetAttribute(gemm2_kernel, cudaFuncAttributeMaxDynamicSharedMemorySize, 3 * S2_STG);
        attr_done = 1;
    }

    zero_kernel<<<1, 32>>>();
    convert_x_kernel<<<(N_TOK * DIM / 4) / 256, 256>>>(x);
    convert_w_kernel<<<dim3((DIM * HID / 4) / 256, 27), 256>>>(Wg, Wu, Wd, sg, su, sd);
    router_kernel<<<N_TOK / 32, 256>>>(x, Wr, lt, li);
    dispatch_kernel<<<N_TOK / 256, 256>>>();

    gemm1_kernel<<<dim3(16, 32, NSEG), 256, 3 * S1_STG>>>();
    gemm2_kernel<<<dim3(16, 32, NSEG), 256, 3 * S2_STG>>>();
    combine_kernel<<<(N_TOK * (DIM / 4)) / 256, 256>>>(out);
}

// round 10
// speedup vs baseline: 5.5635x; 1.0199x over previous
#include <cuda_runtime.h>
#include <cuda_fp16.h>
#include <cstdint>

#define N_TOK 4096
#define DIM   1024
#define HID   1024
#define NE    8
#define NSEG  9

// ---------------- scratch ---------------------------------------------------
__device__ int   g_cnt[NSEG];
__device__ int   g_assign_token[NE * N_TOK];
__device__ int   g_assign_slot [NE * N_TOK];
__device__ int   g_top_e[N_TOK * 2];
__device__ float g_top_w[N_TOK * 2];
__device__ __half g_Xf[(size_t)N_TOK * DIM];
// 27 matrices [k][n]: Wg[0..7], Wu[8..15], Wd[16..23], sg=24, su=25, sd=26
__device__ __half g_Wf[(size_t)27 * DIM * HID];
__device__ __half g_Hf[(size_t)NSEG * N_TOK * HID];
__device__ float g_rbuf[(size_t)3 * N_TOK * DIM];

// ---------------- helpers ---------------------------------------------------
__device__ __forceinline__ uint32_t smem_u32(const void* p) {
    uint32_t a;
    asm("{ .reg .u64 t; cvta.to.shared.u64 t, %1; cvt.u32.u64 %0, t; }"
        : "=r"(a) : "l"(p));
    return a;
}
#define CP_ASYNC16(dst, src) \
    asm volatile("cp.async.cg.shared.global [%0], [%1], 16;" :: "r"(dst), "l"(src))
#define CP_COMMIT() asm volatile("cp.async.commit_group;" ::: "memory")
#define CP_WAIT(n)  asm volatile("cp.async.wait_group %0;" :: "n"(n) : "memory")

__device__ __forceinline__ void ldsm_x4(uint32_t* r, uint32_t addr) {
    asm volatile("ldmatrix.sync.aligned.m8n8.x4.shared.b16 {%0,%1,%2,%3}, [%4];"
        : "=r"(r[0]), "=r"(r[1]), "=r"(r[2]), "=r"(r[3]) : "r"(addr));
}
__device__ __forceinline__ void ldsm_x2_t(uint32_t* r, uint32_t addr) {
    asm volatile("ldmatrix.sync.aligned.m8n8.x2.trans.shared.b16 {%0,%1}, [%2];"
        : "=r"(r[0]), "=r"(r[1]) : "r"(addr));
}
__device__ __forceinline__ void mma_f16(float* d, const uint32_t* a, const uint32_t* b) {
    asm volatile(
        "mma.sync.aligned.m16n8k16.row.col.f32.f16.f16.f32 "
        "{%0,%1,%2,%3}, {%4,%5,%6,%7}, {%8,%9}, {%0,%1,%2,%3};"
        : "+f"(d[0]), "+f"(d[1]), "+f"(d[2]), "+f"(d[3])
        : "r"(a[0]), "r"(a[1]), "r"(a[2]), "r"(a[3]), "r"(b[0]), "r"(b[1]));
}
__device__ __forceinline__ float silu(float g) { return g / (1.f + __expf(-g)); }

__device__ __forceinline__ const float* pick_src(
    int m, const float* Wg, const float* Wu, const float* Wd,
    const float* sg, const float* su, const float* sd)
{
    if (m < 8)  return Wg + (size_t)m * DIM * HID;
    if (m < 16) return Wu + (size_t)(m - 8) * DIM * HID;
    if (m < 24) return Wd + (size_t)(m - 16) * DIM * HID;
    if (m == 24) return sg;
    if (m == 25) return su;
    return sd;
}

// ---------------- small kernels ---------------------------------------------
__global__ void zero_kernel() {
    int t = threadIdx.x;
    if (t < NE) g_cnt[t] = 0;
    if (t == NE) g_cnt[NE] = N_TOK;
}

__global__ void convert_x_kernel(const float* __restrict__ x) {
    size_t i4 = (size_t)blockIdx.x * 256 + threadIdx.x;
    float4 v = ((const float4*)x)[i4];
    __half2 a = __floats2half2_rn(v.x, v.y);
    __half2 b = __floats2half2_rn(v.z, v.w);
    ((uint2*)g_Xf)[i4] = make_uint2(*(uint32_t*)&a, *(uint32_t*)&b);
}

__global__ void convert_w_kernel(
    const float* __restrict__ Wg, const float* __restrict__ Wu,
    const float* __restrict__ Wd, const float* __restrict__ sg,
    const float* __restrict__ su, const float* __restrict__ sd)
{
    int m = blockIdx.y;
    const float* src = pick_src(m, Wg, Wu, Wd, sg, su, sd);
    size_t i4 = (size_t)blockIdx.x * 256 + threadIdx.x;
    float4 v = ((const float4*)src)[i4];
    __half2 a = __floats2half2_rn(v.x, v.y);
    __half2 b = __floats2half2_rn(v.z, v.w);
    size_t o = (size_t)m * (DIM * HID / 4) + i4;
    ((uint2*)g_Wf)[o] = make_uint2(*(uint32_t*)&a, *(uint32_t*)&b);
}

// router: 1 token per warp, 512 blocks (4 waves) for latency hiding
__global__ __launch_bounds__(256, 4) void router_kernel(
    const float* __restrict__ X, const float* __restrict__ Wr,
    const float* __restrict__ loop_table, const int* __restrict__ loop_idx)
{
    __shared__ float4 sW[NE][256];
    __shared__ float s_bias[NE];
    const int tid = threadIdx.x, warp = tid >> 5, lane = tid & 31;

    for (int i = tid; i < NE * 256; i += 256) {
        int e = i >> 8, k4 = i & 255;
        sW[e][k4] = make_float4(Wr[(size_t)(k4 * 4 + 0) * NE + e],
                                Wr[(size_t)(k4 * 4 + 1) * NE + e],
                                Wr[(size_t)(k4 * 4 + 2) * NE + e],
                                Wr[(size_t)(k4 * 4 + 3) * NE + e]);
    }
    const float* le = loop_table + (size_t)loop_idx[0] * DIM;
    float b = 0.f;
    for (int d = lane; d < DIM; d += 32)
        b += le[d] * Wr[(size_t)(DIM + d) * NE + warp];
    #pragma unroll
    for (int o = 16; o; o >>= 1) b += __shfl_xor_sync(~0u, b, o);
    if (lane == 0) s_bias[warp] = b;
    __syncthreads();

    const int t = blockIdx.x * 8 + warp;
    const float4* xr = (const float4*)(X + (size_t)t * DIM);
    float acc[NE];
    #pragma unroll
    for (int e = 0; e < NE; e++) acc[e] = 0.f;
    #pragma unroll 1
    for (int i = 0; i < 8; i++) {
        float4 xv = xr[lane + 32 * i];
        const float4* swp = &sW[0][lane + 32 * i];
        #pragma unroll
        for (int e = 0; e < NE; e++) {
            float4 w = swp[e * 256];
            acc[e] += xv.x * w.x + xv.y * w.y + xv.z * w.z + xv.w * w.w;
        }
    }
    #pragma unroll
    for (int e = 0; e < NE; e++)
        #pragma unroll
        for (int o = 16; o; o >>= 1) acc[e] += __shfl_xor_sync(~0u, acc[e], o);

    if (lane == 0) {
        float p[NE];
        #pragma unroll
        for (int e = 0; e < NE; e++)
            p[e] = 1.f / (1.f + expf(-(acc[e] + s_bias[e])));
        int i0 = 0; float v0 = p[0];
        #pragma unroll
        for (int e = 1; e < NE; e++) if (p[e] > v0) { v0 = p[e]; i0 = e; }
        int i1 = -1; float v1 = -1e30f;
        #pragma unroll
        for (int e = 0; e < NE; e++) {
            if (e == i0) continue;
            if (p[e] > v1) { v1 = p[e]; i1 = e; }
        }
        g_top_e[t * 2 + 0] = i0;  g_top_e[t * 2 + 1] = i1;
        g_top_w[t * 2 + 0] = v0;  g_top_w[t * 2 + 1] = v1;
    }
}

__global__ void dispatch_kernel() {
    int t = blockIdx.x * blockDim.x + threadIdx.x;
    if (t >= N_TOK) return;
    #pragma unroll
    for (int k = 0; k < 2; k++) {
        int e = g_top_e[t * 2 + k];
        int pos = atomicAdd(&g_cnt[e], 1);
        g_assign_token[e * N_TOK + pos] = t;
        g_assign_slot [e * N_TOK + pos] = k;
    }
}

// ---------------- GEMM1: X @ {Wg,Wu}[e], fused SiLU -> fp16 h ---------------
#define S1_A  0u
#define S1_G  6144u
#define S1_U  8448u
#define S1_STG 10752u

__global__ __launch_bounds__(256) void gemm1_kernel() {
    extern __shared__ char sm[];
    __shared__ int s_token[128];

    const int e   = blockIdx.z;
    const int cnt = g_cnt[e];
    const int m0  = blockIdx.y * 128;
    if (m0 >= cnt) return;
    const int n0  = blockIdx.x * 64;
    const int tid = threadIdx.x, wid = tid >> 5, lane = tid & 31;

    const int ig = (e < NE) ? e : 24;
    const int iu = (e < NE) ? 8 + e : 25;

    if (tid < 128) {
        int r = m0 + tid;
        s_token[tid] = (e < NE) ? ((r < cnt) ? g_assign_token[e * N_TOK + r] : 0) : r;
    }
    __syncthreads();
    const uint32_t sb = smem_u32(sm);

    const char* wg = (const char*)(g_Wf + (size_t)ig * DIM * HID);
    const char* wu = (const char*)(g_Wf + (size_t)iu * DIM * HID);

    const int ar = tid >> 1, ahalf = tid & 1;
    const char* aSrc = (const char*)(g_Xf + (size_t)s_token[ar] * DIM) + ahalf * 16;
    const uint32_t aDst = sb + S1_A + ar * 48 + ahalf * 16;
    const int brow = (tid & 127) >> 3, bc = (tid & 7) * 16;
    const bool isG = tid < 128;
    const char* bSrc = (isG ? wg : wu) + (size_t)brow * HID * 2 + n0 * 2 + bc;
    const uint32_t bDst = sb + (isG ? S1_G : S1_U) + brow * 144 + bc;

#define G_LOAD(k0, buf) do { \
        uint32_t _o = (uint32_t)(buf) * S1_STG; \
        size_t _bk = (size_t)(k0) * HID * 2; \
        CP_ASYNC16(aDst + _o, aSrc + (size_t)(k0) * 2); \
        CP_ASYNC16(bDst + _o, bSrc + _bk); \
        CP_COMMIT(); } while (0)

    const int wm = (wid & 3) * 32, wn = (wid >> 2) * 32;
    const int am = (lane & 7) + ((lane >> 3) & 1) * 8;
    const uint32_t ako = (lane >> 4) * 16;
    const uint32_t aB = sb + S1_A + (wm + am) * 48 + ako;
    const int bk = lane & 15;
    const uint32_t bG = sb + S1_G + bk * 144 + wn * 2;
    const uint32_t bU = sb + S1_U + bk * 144 + wn * 2;

    float accG[2][4][4], accU[2][4][4];
    #pragma unroll
    for (int i = 0; i < 2; i++)
        #pragma unroll
        for (int j = 0; j < 4; j++)
            #pragma unroll
            for (int q = 0; q < 4; q++) { accG[i][j][q] = 0.f; accU[i][j][q] = 0.f; }

    G_LOAD(0, 0);
    G_LOAD(16, 1);
    CP_WAIT(1); __syncthreads();

    int cur = 0;
    for (int s = 0; s < 64; s++) {
        int ldb = cur + 2; if (ldb >= 3) ldb -= 3;
        if (s + 2 < 64) G_LOAD((s + 2) * 16, ldb);

        const uint32_t off = (uint32_t)cur * S1_STG;
        uint32_t a[2][4], bg[4][2], bu[4][2];
        #pragma unroll
        for (int i = 0; i < 2; i++) ldsm_x4(a[i], aB + off + i * 768);
        #pragma unroll
        for (int j = 0; j < 4; j++) {
            ldsm_x2_t(bg[j], bG + off + j * 16);
            ldsm_x2_t(bu[j], bU + off + j * 16);
        }
        #pragma unroll
        for (int i = 0; i < 2; i++)
            #pragma unroll
            for (int j = 0; j < 4; j++) {
                mma_f16(accG[i][j], a[i], bg[j]);
                mma_f16(accU[i][j], a[i], bu[j]);
            }
        if (s + 2 < 64) CP_WAIT(1); else CP_WAIT(0);
        __syncthreads();
        cur++; if (cur == 3) cur = 0;
    }

    const int qr = lane >> 2, r4 = lane & 3;
    #pragma unroll
    for (int i = 0; i < 2; i++) {
        const int lr0 = wm + i * 16 + qr, lr1 = lr0 + 8;
        const bool ok0 = (m0 + lr0) < cnt, ok1 = (m0 + lr1) < cnt;
        __half* d0 = g_Hf + ((size_t)e * N_TOK + m0 + lr0) * HID + n0;
        __half* d1 = g_Hf + ((size_t)e * N_TOK + m0 + lr1) * HID + n0;
        #pragma unroll
        for (int j = 0; j < 4; j++) {
            const int col = wn + j * 8 + r4 * 2;
            float h00 = silu(accG[i][j][0]) * accU[i][j][0];
            float h01 = silu(accG[i][j][1]) * accU[i][j][1];
            float h10 = silu(accG[i][j][2]) * accU[i][j][2];
            float h11 = silu(accG[i][j][3]) * accU[i][j][3];
            if (ok0) *(__half2*)(d0 + col) = __floats2half2_rn(h00, h01);
            if (ok1) *(__half2*)(d1 + col) = __floats2half2_rn(h10, h11);
        }
    }
#undef G_LOAD
}

// ---------------- GEMM2: h @ Wd[e] -> scattered fp32 rbuf -------------------
#define S2_A  0u
#define S2_B  6144u
#define S2_STG 8448u

__global__ __launch_bounds__(256) void gemm2_kernel() {
    extern __shared__ char sm[];
    __shared__ int s_dst[128];

    const int e   = blockIdx.z;
    const int cnt = g_cnt[e];
    const int m0  = blockIdx.y * 128;
    if (m0 >= cnt) return;
    const int n0  = blockIdx.x * 64;
    const int tid = threadIdx.x, wid = tid >> 5, lane = tid & 31;

    const int id = (e < NE) ? 16 + e : 26;

    if (tid < 128) {
        int r = m0 + tid, dst = 0;
        if (r < cnt) {
            if (e < NE)
                dst = g_assign_slot[e * N_TOK + r] * N_TOK + g_assign_token[e * N_TOK + r];
            else
                dst = 2 * N_TOK + r;
        }
        s_dst[tid] = dst;
    }
    __syncthreads();
    const uint32_t sb = smem_u32(sm);

    const char* wd = (const char*)(g_Wf + (size_t)id * DIM * HID);

    const int ar = tid >> 1, ahalf = tid & 1;
    const char* aSrc = (const char*)(g_Hf + ((size_t)e * N_TOK + m0 + ar) * HID) + ahalf * 16;
    const uint32_t aDst = sb + S2_A + ar * 48 + ahalf * 16;
    const int brow = (tid & 127) >> 3, bc = (tid & 7) * 16;
    const char* bSrc = wd + (size_t)brow * DIM * 2 + n0 * 2 + bc;
    const uint32_t bDst = sb + S2_B + brow * 144 + bc;
    const bool bAct = tid < 128;

#define G_LOAD(k0, buf) do { \
        uint32_t _o = (uint32_t)(buf) * S2_STG; \
        size_t _bk = (size_t)(k0) * DIM * 2; \
        CP_ASYNC16(aDst + _o, aSrc + (size_t)(k0) * 2); \
        if (bAct) CP_ASYNC16(bDst + _o, bSrc + _bk); \
        CP_COMMIT(); } while (0)

    const int wm = (wid & 3) * 32, wn = (wid >> 2) * 32;
    const int am = (lane & 7) + ((lane >> 3) & 1) * 8;
    const uint32_t ako = (lane >> 4) * 16;
    const uint32_t aB = sb + S2_A + (wm + am) * 48 + ako;
    const int bk = lane & 15;
    const uint32_t bB = sb + S2_B + bk * 144 + wn * 2;

    float acc[2][4][4];
    #pragma unroll
    for (int i = 0; i < 2; i++)
        #pragma unroll
        for (int j = 0; j < 4; j++)
            #pragma unroll
            for (int q = 0; q < 4; q++) acc[i][j][q] = 0.f;

    G_LOAD(0, 0);
    G_LOAD(16, 1);
    CP_WAIT(1); __syncthreads();

    int cur = 0;
    for (int s = 0; s < 64; s++) {
        int ldb = cur + 2; if (ldb >= 3) ldb -= 3;
        if (s + 2 < 64) G_LOAD((s + 2) * 16, ldb);

        const uint32_t off = (uint32_t)cur * S2_STG;
        uint32_t a[2][4], b[4][2];
        #pragma unroll
        for (int i = 0; i < 2; i++) ldsm_x4(a[i], aB + off + i * 768);
        #pragma unroll
        for (int j = 0; j < 4; j++) ldsm_x2_t(b[j], bB + off + j * 16);
        #pragma unroll
        for (int i = 0; i < 2; i++)
            #pragma unroll
            for (int j = 0; j < 4; j++)
                mma_f16(acc[i][j], a[i], b[j]);
        if (s + 2 < 64) CP_WAIT(1); else CP_WAIT(0);
        __syncthreads();
        cur++; if (cur == 3) cur = 0;
    }

    const int qr = lane >> 2, r4 = lane & 3;
    #pragma unroll
    for (int i = 0; i < 2; i++) {
        const int lr0 = wm + i * 16 + qr, lr1 = lr0 + 8;
        const bool ok0 = (m0 + lr0) < cnt, ok1 = (m0 + lr1) < cnt;
        float* d0 = g_rbuf + (size_t)s_dst[lr0] * DIM + n0;
        float* d1 = g_rbuf + (size_t)s_dst[lr1] * DIM + n0;
        #pragma unroll
        for (int j = 0; j < 4; j++) {
            const int col = wn + j * 8 + r4 * 2;
            if (ok0) *(float2*)(d0 + col) = make_float2(acc[i][j][0], acc[i][j][1]);
            if (ok1) *(float2*)(d1 + col) = make_float2(acc[i][j][2], acc[i][j][3]);
        }
    }
#undef G_LOAD
}

// ---------------- combine ---------------------------------------------------
__global__ void combine_kernel(float* __restrict__ out) {
    int i4 = blockIdx.x * 256 + threadIdx.x;
    int t  = i4 >> 8;
    float w0 = g_top_w[2 * t], w1 = g_top_w[2 * t + 1];
    float4 a = ((const float4*)g_rbuf)[i4];
    float4 b = ((const float4*)g_rbuf)[(size_t)(N_TOK * DIM / 4) + i4];
    float4 c = ((const float4*)g_rbuf)[(size_t)(2 * N_TOK * DIM / 4) + i4];
    float4 o;
    o.x = c.x + w0 * a.x + w1 * b.x;
    o.y = c.y + w0 * a.y + w1 * b.y;
    o.z = c.z + w0 * a.z + w1 * b.z;
    o.w = c.w + w0 * a.w + w1 * b.w;
    ((float4*)out)[i4] = o;
}

// ---------------- launch ----------------------------------------------------
extern "C" void kernel_launch(void* const* d_in, const int* in_sizes, int n_in,
                              void* d_out, int out_size)
{
    const float* x  = (const float*)d_in[0];
    const float* sg = (const float*)d_in[1];
    const float* su = (const float*)d_in[2];
    const float* sd = (const float*)d_in[3];
    const float* Wg = (const float*)d_in[4];
    const float* Wu = (const float*)d_in[5];
    const float* Wd = (const float*)d_in[6];
    const float* Wr = (const float*)d_in[7];
    const float* lt = (const float*)d_in[8];
    const int*   li = (const int*)d_in[9];
    float* out = (float*)d_out;
    (void)in_sizes; (void)n_in; (void)out_size;

    static cudaStream_t s2 = nullptr;
    static cudaEvent_t evFork = nullptr, evJoin = nullptr;
    static int init_done = 0;
    if (!init_done) {
        cudaFuncSetAttribute(gemm1_kernel, cudaFuncAttributeMaxDynamicSharedMemorySize, 3 * S1_STG);
        cudaFuncSetAttribute(gemm2_kernel, cudaFuncAttributeMaxDynamicSharedMemorySize, 3 * S2_STG);
        cudaStreamCreateWithFlags(&s2, cudaStreamNonBlocking);
        cudaEventCreateWithFlags(&evFork, cudaEventDisableTiming);
        cudaEventCreateWithFlags(&evJoin, cudaEventDisableTiming);
        init_done = 1;
    }

    // main (capture) stream: routing chain; s2: data conversion — independent.
    cudaEventRecord(evFork, 0);
    cudaStreamWaitEvent(s2, evFork, 0);

    zero_kernel<<<1, 32>>>();
    router_kernel<<<N_TOK / 8, 256>>>(x, Wr, lt, li);
    dispatch_kernel<<<N_TOK / 256, 256>>>();

    convert_x_kernel<<<(N_TOK * DIM / 4) / 256, 256, 0, s2>>>(x);
    convert_w_kernel<<<dim3((DIM * HID / 4) / 256, 27), 256, 0, s2>>>(Wg, Wu, Wd, sg, su, sd);
    cudaEventRecord(evJoin, s2);
    cudaStreamWaitEvent(0, evJoin, 0);

    gemm1_kernel<<<dim3(16, 32, NSEG), 256, 3 * S1_STG>>>();
    gemm2_kernel<<<dim3(16, 32, NSEG), 256, 3 * S2_STG>>>();
    combine_kernel<<<(N_TOK * (DIM / 4)) / 256, 256>>>(out);
}

// round 11
// speedup vs baseline: 5.5840x; 1.0037x over previous
#include <cuda_runtime.h>
#include <cuda_fp16.h>
#include <cstdint>

#define N_TOK 4096
#define DIM   1024
#define HID   1024
#define NE    8
#define NSEG  9

// ---------------- scratch ---------------------------------------------------
__device__ int   g_cnt[NSEG];
__device__ int   g_assign_token[NE * N_TOK];
__device__ int   g_assign_slot [NE * N_TOK];
__device__ int   g_top_e[N_TOK * 2];
__device__ float g_top_w[N_TOK * 2];
__device__ __half g_Xf[(size_t)N_TOK * DIM];
// 27 matrices [k][n]: Wg[0..7], Wu[8..15], Wd[16..23], sg=24, su=25, sd=26
__device__ __half g_Wf[(size_t)27 * DIM * HID];
__device__ __half g_Hf[(size_t)NSEG * N_TOK * HID];
__device__ float g_rbuf[(size_t)3 * N_TOK * DIM];

// ---------------- helpers ---------------------------------------------------
__device__ __forceinline__ uint32_t smem_u32(const void* p) {
    uint32_t a;
    asm("{ .reg .u64 t; cvta.to.shared.u64 t, %1; cvt.u32.u64 %0, t; }"
        : "=r"(a) : "l"(p));
    return a;
}
#define CP_ASYNC16(dst, src) \
    asm volatile("cp.async.cg.shared.global [%0], [%1], 16;" :: "r"(dst), "l"(src))
#define CP_COMMIT() asm volatile("cp.async.commit_group;" ::: "memory")
#define CP_WAIT(n)  asm volatile("cp.async.wait_group %0;" :: "n"(n) : "memory")

__device__ __forceinline__ void ldsm_x4(uint32_t* r, uint32_t addr) {
    asm volatile("ldmatrix.sync.aligned.m8n8.x4.shared.b16 {%0,%1,%2,%3}, [%4];"
        : "=r"(r[0]), "=r"(r[1]), "=r"(r[2]), "=r"(r[3]) : "r"(addr));
}
__device__ __forceinline__ void ldsm_x2_t(uint32_t* r, uint32_t addr) {
    asm volatile("ldmatrix.sync.aligned.m8n8.x2.trans.shared.b16 {%0,%1}, [%2];"
        : "=r"(r[0]), "=r"(r[1]) : "r"(addr));
}
__device__ __forceinline__ void mma_f16(float* d, const uint32_t* a, const uint32_t* b) {
    asm volatile(
        "mma.sync.aligned.m16n8k16.row.col.f32.f16.f16.f32 "
        "{%0,%1,%2,%3}, {%4,%5,%6,%7}, {%8,%9}, {%0,%1,%2,%3};"
        : "+f"(d[0]), "+f"(d[1]), "+f"(d[2]), "+f"(d[3])
        : "r"(a[0]), "r"(a[1]), "r"(a[2]), "r"(a[3]), "r"(b[0]), "r"(b[1]));
}
__device__ __forceinline__ float silu(float g) { return g / (1.f + __expf(-g)); }

__device__ __forceinline__ const float* pick_src(
    int m, const float* Wg, const float* Wu, const float* Wd,
    const float* sg, const float* su, const float* sd)
{
    if (m < 8)  return Wg + (size_t)m * DIM * HID;
    if (m < 16) return Wu + (size_t)(m - 8) * DIM * HID;
    if (m < 24) return Wd + (size_t)(m - 16) * DIM * HID;
    if (m == 24) return sg;
    if (m == 25) return su;
    return sd;
}

__device__ __forceinline__ void convert_one(const float* __restrict__ src,
                                            int m, size_t i4)
{
    float4 v = ((const float4*)src)[i4];
    __half2 a = __floats2half2_rn(v.x, v.y);
    __half2 b = __floats2half2_rn(v.z, v.w);
    size_t o = (size_t)m * (DIM * HID / 4) + i4;
    ((uint2*)g_Wf)[o] = make_uint2(*(uint32_t*)&a, *(uint32_t*)&b);
}

// ---------------- small kernels ---------------------------------------------
__global__ void zero_kernel() {
    int t = threadIdx.x;
    if (t < NE) g_cnt[t] = 0;
    if (t == NE) g_cnt[NE] = N_TOK;
}

__global__ void convert_x_kernel(const float* __restrict__ x) {
    size_t i4 = (size_t)blockIdx.x * 256 + threadIdx.x;
    float4 v = ((const float4*)x)[i4];
    __half2 a = __floats2half2_rn(v.x, v.y);
    __half2 b = __floats2half2_rn(v.z, v.w);
    ((uint2*)g_Xf)[i4] = make_uint2(*(uint32_t*)&a, *(uint32_t*)&b);
}

// gate/up matrices only (18): indices 0..15, 24, 25
__global__ void convert_w_gu_kernel(
    const float* __restrict__ Wg, const float* __restrict__ Wu,
    const float* __restrict__ sg, const float* __restrict__ su)
{
    int by = blockIdx.y;
    int m = (by < 16) ? by : 24 + (by - 16);
    const float* src;
    if      (by < 8)  src = Wg + (size_t)by * DIM * HID;
    else if (by < 16) src = Wu + (size_t)(by - 8) * DIM * HID;
    else if (by == 16) src = sg;
    else               src = su;
    convert_one(src, m, (size_t)blockIdx.x * 256 + threadIdx.x);
}

// down matrices only (9): indices 16..23, 26
__global__ void convert_w_d_kernel(
    const float* __restrict__ Wd, const float* __restrict__ sd)
{
    int by = blockIdx.y;
    int m = (by < 8) ? 16 + by : 26;
    const float* src = (by < 8) ? Wd + (size_t)by * DIM * HID : sd;
    convert_one(src, m, (size_t)blockIdx.x * 256 + threadIdx.x);
}

// router: 1 token per warp, 512 blocks
__global__ __launch_bounds__(256, 4) void router_kernel(
    const float* __restrict__ X, const float* __restrict__ Wr,
    const float* __restrict__ loop_table, const int* __restrict__ loop_idx)
{
    __shared__ float4 sW[NE][256];
    __shared__ float s_bias[NE];
    const int tid = threadIdx.x, warp = tid >> 5, lane = tid & 31;

    for (int i = tid; i < NE * 256; i += 256) {
        int e = i >> 8, k4 = i & 255;
        sW[e][k4] = make_float4(Wr[(size_t)(k4 * 4 + 0) * NE + e],
                                Wr[(size_t)(k4 * 4 + 1) * NE + e],
                                Wr[(size_t)(k4 * 4 + 2) * NE + e],
                                Wr[(size_t)(k4 * 4 + 3) * NE + e]);
    }
    const float* le = loop_table + (size_t)loop_idx[0] * DIM;
    float b = 0.f;
    for (int d = lane; d < DIM; d += 32)
        b += le[d] * Wr[(size_t)(DIM + d) * NE + warp];
    #pragma unroll
    for (int o = 16; o; o >>= 1) b += __shfl_xor_sync(~0u, b, o);
    if (lane == 0) s_bias[warp] = b;
    __syncthreads();

    const int t = blockIdx.x * 8 + warp;
    const float4* xr = (const float4*)(X + (size_t)t * DIM);
    float acc[NE];
    #pragma unroll
    for (int e = 0; e < NE; e++) acc[e] = 0.f;
    #pragma unroll 1
    for (int i = 0; i < 8; i++) {
        float4 xv = xr[lane + 32 * i];
        const float4* swp = &sW[0][lane + 32 * i];
        #pragma unroll
        for (int e = 0; e < NE; e++) {
            float4 w = swp[e * 256];
            acc[e] += xv.x * w.x + xv.y * w.y + xv.z * w.z + xv.w * w.w;
        }
    }
    #pragma unroll
    for (int e = 0; e < NE; e++)
        #pragma unroll
        for (int o = 16; o; o >>= 1) acc[e] += __shfl_xor_sync(~0u, acc[e], o);

    if (lane == 0) {
        float p[NE];
        #pragma unroll
        for (int e = 0; e < NE; e++)
            p[e] = 1.f / (1.f + expf(-(acc[e] + s_bias[e])));
        int i0 = 0; float v0 = p[0];
        #pragma unroll
        for (int e = 1; e < NE; e++) if (p[e] > v0) { v0 = p[e]; i0 = e; }
        int i1 = -1; float v1 = -1e30f;
        #pragma unroll
        for (int e = 0; e < NE; e++) {
            if (e == i0) continue;
            if (p[e] > v1) { v1 = p[e]; i1 = e; }
        }
        g_top_e[t * 2 + 0] = i0;  g_top_e[t * 2 + 1] = i1;
        g_top_w[t * 2 + 0] = v0;  g_top_w[t * 2 + 1] = v1;
    }
}

__global__ void dispatch_kernel() {
    int t = blockIdx.x * blockDim.x + threadIdx.x;
    if (t >= N_TOK) return;
    #pragma unroll
    for (int k = 0; k < 2; k++) {
        int e = g_top_e[t * 2 + k];
        int pos = atomicAdd(&g_cnt[e], 1);
        g_assign_token[e * N_TOK + pos] = t;
        g_assign_slot [e * N_TOK + pos] = k;
    }
}

// ---------------- GEMM1: X @ {Wg,Wu}[e], fused SiLU -> fp16 h ---------------
#define S1_A  0u
#define S1_G  6144u
#define S1_U  8448u
#define S1_STG 10752u

__global__ __launch_bounds__(256) void gemm1_kernel() {
    extern __shared__ char sm[];
    __shared__ int s_token[128];

    const int e   = blockIdx.z;
    const int cnt = g_cnt[e];
    const int m0  = blockIdx.y * 128;
    if (m0 >= cnt) return;
    const int n0  = blockIdx.x * 64;
    const int tid = threadIdx.x, wid = tid >> 5, lane = tid & 31;

    const int ig = (e < NE) ? e : 24;
    const int iu = (e < NE) ? 8 + e : 25;

    if (tid < 128) {
        int r = m0 + tid;
        s_token[tid] = (e < NE) ? ((r < cnt) ? g_assign_token[e * N_TOK + r] : 0) : r;
    }
    __syncthreads();
    const uint32_t sb = smem_u32(sm);

    const char* wg = (const char*)(g_Wf + (size_t)ig * DIM * HID);
    const char* wu = (const char*)(g_Wf + (size_t)iu * DIM * HID);

    const int ar = tid >> 1, ahalf = tid & 1;
    const char* aSrc = (const char*)(g_Xf + (size_t)s_token[ar] * DIM) + ahalf * 16;
    const uint32_t aDst = sb + S1_A + ar * 48 + ahalf * 16;
    const int brow = (tid & 127) >> 3, bc = (tid & 7) * 16;
    const bool isG = tid < 128;
    const char* bSrc = (isG ? wg : wu) + (size_t)brow * HID * 2 + n0 * 2 + bc;
    const uint32_t bDst = sb + (isG ? S1_G : S1_U) + brow * 144 + bc;

#define G_LOAD(k0, buf) do { \
        uint32_t _o = (uint32_t)(buf) * S1_STG; \
        size_t _bk = (size_t)(k0) * HID * 2; \
        CP_ASYNC16(aDst + _o, aSrc + (size_t)(k0) * 2); \
        CP_ASYNC16(bDst + _o, bSrc + _bk); \
        CP_COMMIT(); } while (0)

    const int wm = (wid & 3) * 32, wn = (wid >> 2) * 32;
    const int am = (lane & 7) + ((lane >> 3) & 1) * 8;
    const uint32_t ako = (lane >> 4) * 16;
    const uint32_t aB = sb + S1_A + (wm + am) * 48 + ako;
    const int bk = lane & 15;
    const uint32_t bG = sb + S1_G + bk * 144 + wn * 2;
    const uint32_t bU = sb + S1_U + bk * 144 + wn * 2;

    float accG[2][4][4], accU[2][4][4];
    #pragma unroll
    for (int i = 0; i < 2; i++)
        #pragma unroll
        for (int j = 0; j < 4; j++)
            #pragma unroll
            for (int q = 0; q < 4; q++) { accG[i][j][q] = 0.f; accU[i][j][q] = 0.f; }

    G_LOAD(0, 0);
    G_LOAD(16, 1);
    CP_WAIT(1); __syncthreads();

    int cur = 0;
    for (int s = 0; s < 64; s++) {
        int ldb = cur + 2; if (ldb >= 3) ldb -= 3;
        if (s + 2 < 64) G_LOAD((s + 2) * 16, ldb);

        const uint32_t off = (uint32_t)cur * S1_STG;
        uint32_t a[2][4], bg[4][2], bu[4][2];
        #pragma unroll
        for (int i = 0; i < 2; i++) ldsm_x4(a[i], aB + off + i * 768);
        #pragma unroll
        for (int j = 0; j < 4; j++) {
            ldsm_x2_t(bg[j], bG + off + j * 16);
            ldsm_x2_t(bu[j], bU + off + j * 16);
        }
        #pragma unroll
        for (int i = 0; i < 2; i++)
            #pragma unroll
            for (int j = 0; j < 4; j++) {
                mma_f16(accG[i][j], a[i], bg[j]);
                mma_f16(accU[i][j], a[i], bu[j]);
            }
        if (s + 2 < 64) CP_WAIT(1); else CP_WAIT(0);
        __syncthreads();
        cur++; if (cur == 3) cur = 0;
    }

    const int qr = lane >> 2, r4 = lane & 3;
    #pragma unroll
    for (int i = 0; i < 2; i++) {
        const int lr0 = wm + i * 16 + qr, lr1 = lr0 + 8;
        const bool ok0 = (m0 + lr0) < cnt, ok1 = (m0 + lr1) < cnt;
        __half* d0 = g_Hf + ((size_t)e * N_TOK + m0 + lr0) * HID + n0;
        __half* d1 = g_Hf + ((size_t)e * N_TOK + m0 + lr1) * HID + n0;
        #pragma unroll
        for (int j = 0; j < 4; j++) {
            const int col = wn + j * 8 + r4 * 2;
            float h00 = silu(accG[i][j][0]) * accU[i][j][0];
            float h01 = silu(accG[i][j][1]) * accU[i][j][1];
            float h10 = silu(accG[i][j][2]) * accU[i][j][2];
            float h11 = silu(accG[i][j][3]) * accU[i][j][3];
            if (ok0) *(__half2*)(d0 + col) = __floats2half2_rn(h00, h01);
            if (ok1) *(__half2*)(d1 + col) = __floats2half2_rn(h10, h11);
        }
    }
#undef G_LOAD
}

// ---------------- GEMM2: h @ Wd[e] -> scattered fp32 rbuf -------------------
#define S2_A  0u
#define S2_B  6144u
#define S2_STG 8448u

__global__ __launch_bounds__(256) void gemm2_kernel() {
    extern __shared__ char sm[];
    __shared__ int s_dst[128];

    const int e   = blockIdx.z;
    const int cnt = g_cnt[e];
    const int m0  = blockIdx.y * 128;
    if (m0 >= cnt) return;
    const int n0  = blockIdx.x * 64;
    const int tid = threadIdx.x, wid = tid >> 5, lane = tid & 31;

    const int id = (e < NE) ? 16 + e : 26;

    if (tid < 128) {
        int r = m0 + tid, dst = 0;
        if (r < cnt) {
            if (e < NE)
                dst = g_assign_slot[e * N_TOK + r] * N_TOK + g_assign_token[e * N_TOK + r];
            else
                dst = 2 * N_TOK + r;
        }
        s_dst[tid] = dst;
    }
    __syncthreads();
    const uint32_t sb = smem_u32(sm);

    const char* wd = (const char*)(g_Wf + (size_t)id * DIM * HID);

    const int ar = tid >> 1, ahalf = tid & 1;
    const char* aSrc = (const char*)(g_Hf + ((size_t)e * N_TOK + m0 + ar) * HID) + ahalf * 16;
    const uint32_t aDst = sb + S2_A + ar * 48 + ahalf * 16;
    const int brow = (tid & 127) >> 3, bc = (tid & 7) * 16;
    const char* bSrc = wd + (size_t)brow * DIM * 2 + n0 * 2 + bc;
    const uint32_t bDst = sb + S2_B + brow * 144 + bc;
    const bool bAct = tid < 128;

#define G_LOAD(k0, buf) do { \
        uint32_t _o = (uint32_t)(buf) * S2_STG; \
        size_t _bk = (size_t)(k0) * DIM * 2; \
        CP_ASYNC16(aDst + _o, aSrc + (size_t)(k0) * 2); \
        if (bAct) CP_ASYNC16(bDst + _o, bSrc + _bk); \
        CP_COMMIT(); } while (0)

    const int wm = (wid & 3) * 32, wn = (wid >> 2) * 32;
    const int am = (lane & 7) + ((lane >> 3) & 1) * 8;
    const uint32_t ako = (lane >> 4) * 16;
    const uint32_t aB = sb + S2_A + (wm + am) * 48 + ako;
    const int bk = lane & 15;
    const uint32_t bB = sb + S2_B + bk * 144 + wn * 2;

    float acc[2][4][4];
    #pragma unroll
    for (int i = 0; i < 2; i++)
        #pragma unroll
        for (int j = 0; j < 4; j++)
            #pragma unroll
            for (int q = 0; q < 4; q++) acc[i][j][q] = 0.f;

    G_LOAD(0, 0);
    G_LOAD(16, 1);
    CP_WAIT(1); __syncthreads();

    int cur = 0;
    for (int s = 0; s < 64; s++) {
        int ldb = cur + 2; if (ldb >= 3) ldb -= 3;
        if (s + 2 < 64) G_LOAD((s + 2) * 16, ldb);

        const uint32_t off = (uint32_t)cur * S2_STG;
        uint32_t a[2][4], b[4][2];
        #pragma unroll
        for (int i = 0; i < 2; i++) ldsm_x4(a[i], aB + off + i * 768);
        #pragma unroll
        for (int j = 0; j < 4; j++) ldsm_x2_t(b[j], bB + off + j * 16);
        #pragma unroll
        for (int i = 0; i < 2; i++)
            #pragma unroll
            for (int j = 0; j < 4; j++)
                mma_f16(acc[i][j], a[i], b[j]);
        if (s + 2 < 64) CP_WAIT(1); else CP_WAIT(0);
        __syncthreads();
        cur++; if (cur == 3) cur = 0;
    }

    const int qr = lane >> 2, r4 = lane & 3;
    #pragma unroll
    for (int i = 0; i < 2; i++) {
        const int lr0 = wm + i * 16 + qr, lr1 = lr0 + 8;
        const bool ok0 = (m0 + lr0) < cnt, ok1 = (m0 + lr1) < cnt;
        float* d0 = g_rbuf + (size_t)s_dst[lr0] * DIM + n0;
        float* d1 = g_rbuf + (size_t)s_dst[lr1] * DIM + n0;
        #pragma unroll
        for (int j = 0; j < 4; j++) {
            const int col = wn + j * 8 + r4 * 2;
            if (ok0) *(float2*)(d0 + col) = make_float2(acc[i][j][0], acc[i][j][1]);
            if (ok1) *(float2*)(d1 + col) = make_float2(acc[i][j][2], acc[i][j][3]);
        }
    }
#undef G_LOAD
}

// ---------------- combine ---------------------------------------------------
__global__ void combine_kernel(float* __restrict__ out) {
    int i4 = blockIdx.x * 256 + threadIdx.x;
    int t  = i4 >> 8;
    float w0 = g_top_w[2 * t], w1 = g_top_w[2 * t + 1];
    float4 a = ((const float4*)g_rbuf)[i4];
    float4 b = ((const float4*)g_rbuf)[(size_t)(N_TOK * DIM / 4) + i4];
    float4 c = ((const float4*)g_rbuf)[(size_t)(2 * N_TOK * DIM / 4) + i4];
    float4 o;
    o.x = c.x + w0 * a.x + w1 * b.x;
    o.y = c.y + w0 * a.y + w1 * b.y;
    o.z = c.z + w0 * a.z + w1 * b.z;
    o.w = c.w + w0 * a.w + w1 * b.w;
    ((float4*)out)[i4] = o;
}

// ---------------- launch ----------------------------------------------------
extern "C" void kernel_launch(void* const* d_in, const int* in_sizes, int n_in,
                              void* d_out, int out_size)
{
    const float* x  = (const float*)d_in[0];
    const float* sg = (const float*)d_in[1];
    const float* su = (const float*)d_in[2];
    const float* sd = (const float*)d_in[3];
    const float* Wg = (const float*)d_in[4];
    const float* Wu = (const float*)d_in[5];
    const float* Wd = (const float*)d_in[6];
    const float* Wr = (const float*)d_in[7];
    const float* lt = (const float*)d_in[8];
    const int*   li = (const int*)d_in[9];
    float* out = (float*)d_out;
    (void)in_sizes; (void)n_in; (void)out_size;

    static cudaStream_t s2 = nullptr;
    static cudaEvent_t evFork = nullptr, evGU = nullptr, evD = nullptr;
    static int init_done = 0;
    if (!init_done) {
        cudaFuncSetAttribute(gemm1_kernel, cudaFuncAttributeMaxDynamicSharedMemorySize, 3 * S1_STG);
        cudaFuncSetAttribute(gemm2_kernel, cudaFuncAttributeMaxDynamicSharedMemorySize, 3 * S2_STG);
        cudaStreamCreateWithFlags(&s2, cudaStreamNonBlocking);
        cudaEventCreateWithFlags(&evFork, cudaEventDisableTiming);
        cudaEventCreateWithFlags(&evGU, cudaEventDisableTiming);
        cudaEventCreateWithFlags(&evD, cudaEventDisableTiming);
        init_done = 1;
    }

    // fork: s2 does data conversion; main does routing chain.
    cudaEventRecord(evFork, 0);
    cudaStreamWaitEvent(s2, evFork, 0);

    zero_kernel<<<1, 32>>>();
    router_kernel<<<N_TOK / 8, 256>>>(x, Wr, lt, li);
    dispatch_kernel<<<N_TOK / 256, 256>>>();

    convert_x_kernel<<<(N_TOK * DIM / 4) / 256, 256, 0, s2>>>(x);
    convert_w_gu_kernel<<<dim3((DIM * HID / 4) / 256, 18), 256, 0, s2>>>(Wg, Wu, sg, su);
    cudaEventRecord(evGU, s2);
    convert_w_d_kernel<<<dim3((DIM * HID / 4) / 256, 9), 256, 0, s2>>>(Wd, sd);
    cudaEventRecord(evD, s2);

    // gemm1 needs X + gate/up weights only; Wd conversion overlaps gemm1.
    cudaStreamWaitEvent(0, evGU, 0);
    gemm1_kernel<<<dim3(16, 32, NSEG), 256, 3 * S1_STG>>>();
    cudaStreamWaitEvent(0, evD, 0);
    gemm2_kernel<<<dim3(16, 32, NSEG), 256, 3 * S2_STG>>>();
    combine_kernel<<<(N_TOK * (DIM / 4)) / 256, 256>>>(out);
}

// round 12
// speedup vs baseline: 6.2002x; 1.1103x over previous
#include <cuda_runtime.h>
#include <cuda_fp16.h>
#include <cstdint>

#define N_TOK 4096
#define DIM   1024
#define HID   1024
#define NE    8
#define NSEG  9

// ---------------- scratch ---------------------------------------------------
__device__ int   g_cnt[NSEG];
__device__ int   g_assign_token[NE * N_TOK];
__device__ int   g_assign_slot [NE * N_TOK];
__device__ int   g_top_e[N_TOK * 2];
__device__ float g_top_w[N_TOK * 2];
__device__ __half g_Xf[(size_t)N_TOK * DIM];
// 27 matrices [k][n]: Wg[0..7], Wu[8..15], Wd[16..23], sg=24, su=25, sd=26
__device__ __half g_Wf[(size_t)27 * DIM * HID];
__device__ __half g_Hf[(size_t)NSEG * N_TOK * HID];
__device__ float g_rbuf[(size_t)3 * N_TOK * DIM];

// ---------------- helpers ---------------------------------------------------
__device__ __forceinline__ uint32_t smem_u32(const void* p) {
    uint32_t a;
    asm("{ .reg .u64 t; cvta.to.shared.u64 t, %1; cvt.u32.u64 %0, t; }"
        : "=r"(a) : "l"(p));
    return a;
}
#define CP_ASYNC16(dst, src) \
    asm volatile("cp.async.cg.shared.global [%0], [%1], 16;" :: "r"(dst), "l"(src))
#define CP_COMMIT() asm volatile("cp.async.commit_group;" ::: "memory")
#define CP_WAIT(n)  asm volatile("cp.async.wait_group %0;" :: "n"(n) : "memory")

__device__ __forceinline__ void ldsm_x4(uint32_t* r, uint32_t addr) {
    asm volatile("ldmatrix.sync.aligned.m8n8.x4.shared.b16 {%0,%1,%2,%3}, [%4];"
        : "=r"(r[0]), "=r"(r[1]), "=r"(r[2]), "=r"(r[3]) : "r"(addr));
}
__device__ __forceinline__ void ldsm_x2_t(uint32_t* r, uint32_t addr) {
    asm volatile("ldmatrix.sync.aligned.m8n8.x2.trans.shared.b16 {%0,%1}, [%2];"
        : "=r"(r[0]), "=r"(r[1]) : "r"(addr));
}
__device__ __forceinline__ void mma_f16(float* d, const uint32_t* a, const uint32_t* b) {
    asm volatile(
        "mma.sync.aligned.m16n8k16.row.col.f32.f16.f16.f32 "
        "{%0,%1,%2,%3}, {%4,%5,%6,%7}, {%8,%9}, {%0,%1,%2,%3};"
        : "+f"(d[0]), "+f"(d[1]), "+f"(d[2]), "+f"(d[3])
        : "r"(a[0]), "r"(a[1]), "r"(a[2]), "r"(a[3]), "r"(b[0]), "r"(b[1]));
}
__device__ __forceinline__ float silu(float g) { return g / (1.f + __expf(-g)); }

__device__ __forceinline__ void convert_one(const float* __restrict__ src,
                                            int m, size_t i4)
{
    float4 v = ((const float4*)src)[i4];
    __half2 a = __floats2half2_rn(v.x, v.y);
    __half2 b = __floats2half2_rn(v.z, v.w);
    size_t o = (size_t)m * (DIM * HID / 4) + i4;
    ((uint2*)g_Wf)[o] = make_uint2(*(uint32_t*)&a, *(uint32_t*)&b);
}

// ---------------- small kernels ---------------------------------------------
__global__ void zero_kernel() {
    int t = threadIdx.x;
    if (t < NE) g_cnt[t] = 0;
    if (t == NE) g_cnt[NE] = N_TOK;
}

// 4x ILP converts (MLP=4)
__global__ void convert_x_kernel(const float* __restrict__ x) {
    size_t base = (size_t)blockIdx.x * 1024 + threadIdx.x;
    float4 v[4];
    #pragma unroll
    for (int j = 0; j < 4; j++) v[j] = ((const float4*)x)[base + j * 256];
    #pragma unroll
    for (int j = 0; j < 4; j++) {
        __half2 a = __floats2half2_rn(v[j].x, v[j].y);
        __half2 b = __floats2half2_rn(v[j].z, v[j].w);
        ((uint2*)g_Xf)[base + j * 256] = make_uint2(*(uint32_t*)&a, *(uint32_t*)&b);
    }
}

// gate/up matrices (18): indices 0..15, 24, 25
__global__ void convert_w_gu_kernel(
    const float* __restrict__ Wg, const float* __restrict__ Wu,
    const float* __restrict__ sg, const float* __restrict__ su)
{
    int by = blockIdx.y;
    int m = (by < 16) ? by : 24 + (by - 16);
    const float* src;
    if      (by < 8)  src = Wg + (size_t)by * DIM * HID;
    else if (by < 16) src = Wu + (size_t)(by - 8) * DIM * HID;
    else if (by == 16) src = sg;
    else               src = su;
    size_t base = (size_t)blockIdx.x * 1024 + threadIdx.x;
    #pragma unroll
    for (int j = 0; j < 4; j++) convert_one(src, m, base + j * 256);
}

// down matrices (9): indices 16..23, 26
__global__ void convert_w_d_kernel(
    const float* __restrict__ Wd, const float* __restrict__ sd)
{
    int by = blockIdx.y;
    int m = (by < 8) ? 16 + by : 26;
    const float* src = (by < 8) ? Wd + (size_t)by * DIM * HID : sd;
    size_t base = (size_t)blockIdx.x * 1024 + threadIdx.x;
    #pragma unroll
    for (int j = 0; j < 4; j++) convert_one(src, m, base + j * 256);
}

// router: 1 token per warp, 512 blocks
__global__ __launch_bounds__(256, 4) void router_kernel(
    const float* __restrict__ X, const float* __restrict__ Wr,
    const float* __restrict__ loop_table, const int* __restrict__ loop_idx)
{
    __shared__ float4 sW[NE][256];
    __shared__ float s_bias[NE];
    const int tid = threadIdx.x, warp = tid >> 5, lane = tid & 31;

    for (int i = tid; i < NE * 256; i += 256) {
        int e = i >> 8, k4 = i & 255;
        sW[e][k4] = make_float4(Wr[(size_t)(k4 * 4 + 0) * NE + e],
                                Wr[(size_t)(k4 * 4 + 1) * NE + e],
                                Wr[(size_t)(k4 * 4 + 2) * NE + e],
                                Wr[(size_t)(k4 * 4 + 3) * NE + e]);
    }
    const float* le = loop_table + (size_t)loop_idx[0] * DIM;
    float b = 0.f;
    for (int d = lane; d < DIM; d += 32)
        b += le[d] * Wr[(size_t)(DIM + d) * NE + warp];
    #pragma unroll
    for (int o = 16; o; o >>= 1) b += __shfl_xor_sync(~0u, b, o);
    if (lane == 0) s_bias[warp] = b;
    __syncthreads();

    const int t = blockIdx.x * 8 + warp;
    const float4* xr = (const float4*)(X + (size_t)t * DIM);
    float acc[NE];
    #pragma unroll
    for (int e = 0; e < NE; e++) acc[e] = 0.f;
    #pragma unroll 1
    for (int i = 0; i < 8; i++) {
        float4 xv = xr[lane + 32 * i];
        const float4* swp = &sW[0][lane + 32 * i];
        #pragma unroll
        for (int e = 0; e < NE; e++) {
            float4 w = swp[e * 256];
            acc[e] += xv.x * w.x + xv.y * w.y + xv.z * w.z + xv.w * w.w;
        }
    }
    #pragma unroll
    for (int e = 0; e < NE; e++)
        #pragma unroll
        for (int o = 16; o; o >>= 1) acc[e] += __shfl_xor_sync(~0u, acc[e], o);

    if (lane == 0) {
        float p[NE];
        #pragma unroll
        for (int e = 0; e < NE; e++)
            p[e] = 1.f / (1.f + expf(-(acc[e] + s_bias[e])));
        int i0 = 0; float v0 = p[0];
        #pragma unroll
        for (int e = 1; e < NE; e++) if (p[e] > v0) { v0 = p[e]; i0 = e; }
        int i1 = -1; float v1 = -1e30f;
        #pragma unroll
        for (int e = 0; e < NE; e++) {
            if (e == i0) continue;
            if (p[e] > v1) { v1 = p[e]; i1 = e; }
        }
        g_top_e[t * 2 + 0] = i0;  g_top_e[t * 2 + 1] = i1;
        g_top_w[t * 2 + 0] = v0;  g_top_w[t * 2 + 1] = v1;
    }
}

__global__ void dispatch_kernel() {
    int t = blockIdx.x * blockDim.x + threadIdx.x;
    if (t >= N_TOK) return;
    #pragma unroll
    for (int k = 0; k < 2; k++) {
        int e = g_top_e[t * 2 + k];
        int pos = atomicAdd(&g_cnt[e], 1);
        g_assign_token[e * N_TOK + pos] = t;
        g_assign_slot [e * N_TOK + pos] = k;
    }
}

// ---------------- GEMM1: X @ {Wg,Wu}[e], fused SiLU -> fp16 h ---------------
// Block 128m x 64n, BK=32 per stage, 3-stage. A pitch 80B, B pitch 144B.
#define S1_A  0u
#define S1_G  10240u
#define S1_U  14848u
#define S1_STG 19456u

__global__ __launch_bounds__(256) void gemm1_kernel() {
    extern __shared__ char sm[];
    __shared__ int s_token[128];

    const int e   = blockIdx.z;
    const int cnt = g_cnt[e];
    const int m0  = blockIdx.y * 128;
    if (m0 >= cnt) return;
    const int n0  = blockIdx.x * 64;
    const int tid = threadIdx.x, wid = tid >> 5, lane = tid & 31;

    const int ig = (e < NE) ? e : 24;
    const int iu = (e < NE) ? 8 + e : 25;

    if (tid < 128) {
        int r = m0 + tid;
        s_token[tid] = (e < NE) ? ((r < cnt) ? g_assign_token[e * N_TOK + r] : 0) : r;
    }
    __syncthreads();
    const uint32_t sb = smem_u32(sm);

    const char* wg = (const char*)(g_Wf + (size_t)ig * DIM * HID);
    const char* wu = (const char*)(g_Wf + (size_t)iu * DIM * HID);

    // loaders: 4 cp.async / thread / stage
    const int ar0 = tid >> 2, ac = (tid & 3) * 16;
    const char* aSrc0 = (const char*)(g_Xf + (size_t)s_token[ar0] * DIM) + ac;
    const char* aSrc1 = (const char*)(g_Xf + (size_t)s_token[64 + ar0] * DIM) + ac;
    const uint32_t aDst0 = sb + S1_A + ar0 * 80 + ac;
    const uint32_t aDst1 = sb + S1_A + (64 + ar0) * 80 + ac;
    const int brw = tid >> 3, bcc = (tid & 7) * 16;
    const char* gSrc = wg + (size_t)brw * HID * 2 + n0 * 2 + bcc;
    const char* uSrc = wu + (size_t)brw * HID * 2 + n0 * 2 + bcc;
    const uint32_t gDst = sb + S1_G + brw * 144 + bcc;
    const uint32_t uDst = sb + S1_U + brw * 144 + bcc;

#define G_LOAD(k0, buf) do { \
        uint32_t _o = (uint32_t)(buf) * S1_STG; \
        size_t _ab = (size_t)(k0) * 2; \
        size_t _bb = (size_t)(k0) * HID * 2; \
        CP_ASYNC16(aDst0 + _o, aSrc0 + _ab); \
        CP_ASYNC16(aDst1 + _o, aSrc1 + _ab); \
        CP_ASYNC16(gDst + _o, gSrc + _bb); \
        CP_ASYNC16(uDst + _o, uSrc + _bb); \
        CP_COMMIT(); } while (0)

    const int wm = (wid & 3) * 32, wn = (wid >> 2) * 32;
    const int am = (lane & 7) + ((lane >> 3) & 1) * 8;
    const uint32_t ako = (lane >> 4) * 16;
    const uint32_t aB = sb + S1_A + (wm + am) * 80 + ako;
    const int bk = lane & 15;
    const uint32_t bG = sb + S1_G + bk * 144 + wn * 2;
    const uint32_t bU = sb + S1_U + bk * 144 + wn * 2;

    float accG[2][4][4], accU[2][4][4];
    #pragma unroll
    for (int i = 0; i < 2; i++)
        #pragma unroll
        for (int j = 0; j < 4; j++)
            #pragma unroll
            for (int q = 0; q < 4; q++) { accG[i][j][q] = 0.f; accU[i][j][q] = 0.f; }

    G_LOAD(0, 0);
    G_LOAD(32, 1);
    CP_WAIT(1); __syncthreads();

    int cur = 0;
    for (int s = 0; s < 32; s++) {
        int ldb = cur + 2; if (ldb >= 3) ldb -= 3;
        if (s + 2 < 32) G_LOAD((s + 2) * 32, ldb);

        const uint32_t off = (uint32_t)cur * S1_STG;
        #pragma unroll
        for (int ks = 0; ks < 2; ks++) {
            uint32_t a[2][4], bg[4][2], bu[4][2];
            #pragma unroll
            for (int i = 0; i < 2; i++)
                ldsm_x4(a[i], aB + off + ks * 32 + i * 1280);
            #pragma unroll
            for (int j = 0; j < 4; j++) {
                ldsm_x2_t(bg[j], bG + off + ks * 2304 + j * 16);
                ldsm_x2_t(bu[j], bU + off + ks * 2304 + j * 16);
            }
            #pragma unroll
            for (int i = 0; i < 2; i++)
                #pragma unroll
                for (int j = 0; j < 4; j++) {
                    mma_f16(accG[i][j], a[i], bg[j]);
                    mma_f16(accU[i][j], a[i], bu[j]);
                }
        }
        if (s + 2 < 32) CP_WAIT(1); else CP_WAIT(0);
        __syncthreads();
        cur++; if (cur == 3) cur = 0;
    }

    const int qr = lane >> 2, r4 = lane & 3;
    #pragma unroll
    for (int i = 0; i < 2; i++) {
        const int lr0 = wm + i * 16 + qr, lr1 = lr0 + 8;
        const bool ok0 = (m0 + lr0) < cnt, ok1 = (m0 + lr1) < cnt;
        __half* d0 = g_Hf + ((size_t)e * N_TOK + m0 + lr0) * HID + n0;
        __half* d1 = g_Hf + ((size_t)e * N_TOK + m0 + lr1) * HID + n0;
        #pragma unroll
        for (int j = 0; j < 4; j++) {
            const int col = wn + j * 8 + r4 * 2;
            float h00 = silu(accG[i][j][0]) * accU[i][j][0];
            float h01 = silu(accG[i][j][1]) * accU[i][j][1];
            float h10 = silu(accG[i][j][2]) * accU[i][j][2];
            float h11 = silu(accG[i][j][3]) * accU[i][j][3];
            if (ok0) *(__half2*)(d0 + col) = __floats2half2_rn(h00, h01);
            if (ok1) *(__half2*)(d1 + col) = __floats2half2_rn(h10, h11);
        }
    }
#undef G_LOAD
}

// ---------------- GEMM2: h @ Wd[e] -> scattered fp32 rbuf -------------------
// Block 128m x 64n, BK=32 per stage, 3-stage.
#define S2_A  0u
#define S2_B  10240u
#define S2_STG 14848u

__global__ __launch_bounds__(256) void gemm2_kernel() {
    extern __shared__ char sm[];
    __shared__ int s_dst[128];

    const int e   = blockIdx.z;
    const int cnt = g_cnt[e];
    const int m0  = blockIdx.y * 128;
    if (m0 >= cnt) return;
    const int n0  = blockIdx.x * 64;
    const int tid = threadIdx.x, wid = tid >> 5, lane = tid & 31;

    const int id = (e < NE) ? 16 + e : 26;

    if (tid < 128) {
        int r = m0 + tid, dst = 0;
        if (r < cnt) {
            if (e < NE)
                dst = g_assign_slot[e * N_TOK + r] * N_TOK + g_assign_token[e * N_TOK + r];
            else
                dst = 2 * N_TOK + r;
        }
        s_dst[tid] = dst;
    }
    __syncthreads();
    const uint32_t sb = smem_u32(sm);

    const char* wd = (const char*)(g_Wf + (size_t)id * DIM * HID);

    const int ar0 = tid >> 2, ac = (tid & 3) * 16;
    const char* aSrc0 = (const char*)(g_Hf + ((size_t)e * N_TOK + m0 + ar0) * HID) + ac;
    const char* aSrc1 = (const char*)(g_Hf + ((size_t)e * N_TOK + m0 + 64 + ar0) * HID) + ac;
    const uint32_t aDst0 = sb + S2_A + ar0 * 80 + ac;
    const uint32_t aDst1 = sb + S2_A + (64 + ar0) * 80 + ac;
    const int brw = tid >> 3, bcc = (tid & 7) * 16;
    const char* bSrc = wd + (size_t)brw * DIM * 2 + n0 * 2 + bcc;
    const uint32_t bDst = sb + S2_B + brw * 144 + bcc;

#define G_LOAD(k0, buf) do { \
        uint32_t _o = (uint32_t)(buf) * S2_STG; \
        size_t _ab = (size_t)(k0) * 2; \
        size_t _bb = (size_t)(k0) * DIM * 2; \
        CP_ASYNC16(aDst0 + _o, aSrc0 + _ab); \
        CP_ASYNC16(aDst1 + _o, aSrc1 + _ab); \
        CP_ASYNC16(bDst + _o, bSrc + _bb); \
        CP_COMMIT(); } while (0)

    const int wm = (wid & 3) * 32, wn = (wid >> 2) * 32;
    const int am = (lane & 7) + ((lane >> 3) & 1) * 8;
    const uint32_t ako = (lane >> 4) * 16;
    const uint32_t aB = sb + S2_A + (wm + am) * 80 + ako;
    const int bk = lane & 15;
    const uint32_t bB = sb + S2_B + bk * 144 + wn * 2;

    float acc[2][4][4];
    #pragma unroll
    for (int i = 0; i < 2; i++)
        #pragma unroll
        for (int j = 0; j < 4; j++)
            #pragma unroll
            for (int q = 0; q < 4; q++) acc[i][j][q] = 0.f;

    G_LOAD(0, 0);
    G_LOAD(32, 1);
    CP_WAIT(1); __syncthreads();

    int cur = 0;
    for (int s = 0; s < 32; s++) {
        int ldb = cur + 2; if (ldb >= 3) ldb -= 3;
        if (s + 2 < 32) G_LOAD((s + 2) * 32, ldb);

        const uint32_t off = (uint32_t)cur * S2_STG;
        #pragma unroll
        for (int ks = 0; ks < 2; ks++) {
            uint32_t a[2][4], b[4][2];
            #pragma unroll
            for (int i = 0; i < 2; i++)
                ldsm_x4(a[i], aB + off + ks * 32 + i * 1280);
            #pragma unroll
            for (int j = 0; j < 4; j++)
                ldsm_x2_t(b[j], bB + off + ks * 2304 + j * 16);
            #pragma unroll
            for (int i = 0; i < 2; i++)
                #pragma unroll
                for (int j = 0; j < 4; j++)
                    mma_f16(acc[i][j], a[i], b[j]);
        }
        if (s + 2 < 32) CP_WAIT(1); else CP_WAIT(0);
        __syncthreads();
        cur++; if (cur == 3) cur = 0;
    }

    const int qr = lane >> 2, r4 = lane & 3;
    #pragma unroll
    for (int i = 0; i < 2; i++) {
        const int lr0 = wm + i * 16 + qr, lr1 = lr0 + 8;
        const bool ok0 = (m0 + lr0) < cnt, ok1 = (m0 + lr1) < cnt;
        float* d0 = g_rbuf + (size_t)s_dst[lr0] * DIM + n0;
        float* d1 = g_rbuf + (size_t)s_dst[lr1] * DIM + n0;
        #pragma unroll
        for (int j = 0; j < 4; j++) {
            const int col = wn + j * 8 + r4 * 2;
            if (ok0) *(float2*)(d0 + col) = make_float2(acc[i][j][0], acc[i][j][1]);
            if (ok1) *(float2*)(d1 + col) = make_float2(acc[i][j][2], acc[i][j][3]);
        }
    }
#undef G_LOAD
}

// ---------------- combine ---------------------------------------------------
__global__ void combine_kernel(float* __restrict__ out) {
    int i4 = blockIdx.x * 256 + threadIdx.x;
    int t  = i4 >> 8;
    float w0 = g_top_w[2 * t], w1 = g_top_w[2 * t + 1];
    float4 a = ((const float4*)g_rbuf)[i4];
    float4 b = ((const float4*)g_rbuf)[(size_t)(N_TOK * DIM / 4) + i4];
    float4 c = ((const float4*)g_rbuf)[(size_t)(2 * N_TOK * DIM / 4) + i4];
    float4 o;
    o.x = c.x + w0 * a.x + w1 * b.x;
    o.y = c.y + w0 * a.y + w1 * b.y;
    o.z = c.z + w0 * a.z + w1 * b.z;
    o.w = c.w + w0 * a.w + w1 * b.w;
    ((float4*)out)[i4] = o;
}

// ---------------- launch ----------------------------------------------------
extern "C" void kernel_launch(void* const* d_in, const int* in_sizes, int n_in,
                              void* d_out, int out_size)
{
    const float* x  = (const float*)d_in[0];
    const float* sg = (const float*)d_in[1];
    const float* su = (const float*)d_in[2];
    const float* sd = (const float*)d_in[3];
    const float* Wg = (const float*)d_in[4];
    const float* Wu = (const float*)d_in[5];
    const float* Wd = (const float*)d_in[6];
    const float* Wr = (const float*)d_in[7];
    const float* lt = (const float*)d_in[8];
    const int*   li = (const int*)d_in[9];
    float* out = (float*)d_out;
    (void)in_sizes; (void)n_in; (void)out_size;

    static cudaStream_t s2 = nullptr;
    static cudaEvent_t evFork = nullptr, evGU = nullptr, evD = nullptr;
    static int init_done = 0;
    if (!init_done) {
        cudaFuncSetAttribute(gemm1_kernel, cudaFuncAttributeMaxDynamicSharedMemorySize, 3 * S1_STG);
        cudaFuncSetAttribute(gemm2_kernel, cudaFuncAttributeMaxDynamicSharedMemorySize, 3 * S2_STG);
        cudaStreamCreateWithFlags(&s2, cudaStreamNonBlocking);
        cudaEventCreateWithFlags(&evFork, cudaEventDisableTiming);
        cudaEventCreateWithFlags(&evGU, cudaEventDisableTiming);
        cudaEventCreateWithFlags(&evD, cudaEventDisableTiming);
        init_done = 1;
    }

    // fork: s2 does data conversion; main does routing chain.
    cudaEventRecord(evFork, 0);
    cudaStreamWaitEvent(s2, evFork, 0);

    zero_kernel<<<1, 32>>>();
    router_kernel<<<N_TOK / 8, 256>>>(x, Wr, lt, li);
    dispatch_kernel<<<N_TOK / 256, 256>>>();

    convert_x_kernel<<<(N_TOK * DIM / 4) / 1024, 256, 0, s2>>>(x);
    convert_w_gu_kernel<<<dim3((DIM * HID / 4) / 1024, 18), 256, 0, s2>>>(Wg, Wu, sg, su);
    cudaEventRecord(evGU, s2);
    convert_w_d_kernel<<<dim3((DIM * HID / 4) / 1024, 9), 256, 0, s2>>>(Wd, sd);
    cudaEventRecord(evD, s2);

    cudaStreamWaitEvent(0, evGU, 0);
    gemm1_kernel<<<dim3(16, 32, NSEG), 256, 3 * S1_STG>>>();
    cudaStreamWaitEvent(0, evD, 0);
    gemm2_kernel<<<dim3(16, 32, NSEG), 256, 3 * S2_STG>>>();
    combine_kernel<<<(N_TOK * (DIM / 4)) / 256, 256>>>(out);
}